// round 14
// baseline (speedup 1.0000x reference)
#include <cuda_runtime.h>
#include <cuda_bf16.h>
#include <math.h>
#include <stdint.h>

#define BATCH  16
#define SEQ    1024
#define DMODEL 512
#define DINNER 1024
#define DTRANK 32
#define DSTATE 16
#define PREDL  192
#define NUML   96
#define MROWS  (BATCH*SEQ)   // 16384
#define MHALF  (MROWS/2)     // 8192

// ---------------- scratch (device globals; no allocations allowed) ----------
__device__ float g_inT [MROWS*NUML];
__device__ float g_emb [MROWS*DMODEL];
__device__ float g_acc [MROWS*DMODEL];
__device__ float g_acc2[MROWS*DMODEL];
__device__ float g_xz  [MROWS*2*DINNER];
__device__ float g_xz2 [MROWS*2*DINNER];
__device__ float g_xc  [MROWS*DINNER];
__device__ float g_xc2 [MROWS*DINNER];
__device__ float g_xdbl [MROWS*64];
__device__ float g_xdbl2[MROWS*64];
__device__ float g_dtp [MROWS*DINNER*2];   // interleaved (dt, exp(-dt))
__device__ float g_dtp2[MROWS*DINNER*2];
__device__ __nv_bfloat16 g_embh[MROWS*DMODEL];
__device__ __nv_bfloat16 g_embl[MROWS*DMODEL];
__device__ __nv_bfloat16 g_ysh [MROWS*DINNER];
__device__ __nv_bfloat16 g_ysl [MROWS*DINNER];
__device__ __nv_bfloat16 g_ysh2[MROWS*DINNER];
__device__ __nv_bfloat16 g_ysl2[MROWS*DINNER];
__device__ __nv_bfloat16 g_winh[4*2*DINNER*DMODEL];
__device__ __nv_bfloat16 g_winl[4*2*DINNER*DMODEL];
__device__ __nv_bfloat16 g_wouth[4*DMODEL*DINNER];
__device__ __nv_bfloat16 g_woutl[4*DMODEL*DINNER];

__device__ __forceinline__ float silu_f(float x) {
    return x * (1.f / (1.f + __expf(-x)));
}

__device__ __forceinline__ void ldsm_x4(uint32_t (&r)[4], uint32_t addr) {
    asm volatile("ldmatrix.sync.aligned.m8n8.x4.shared.b16 {%0,%1,%2,%3}, [%4];"
                 : "=r"(r[0]), "=r"(r[1]), "=r"(r[2]), "=r"(r[3]) : "r"(addr));
}
__device__ __forceinline__ void mma_bf16(float (&c)[4], const uint32_t (&a)[4],
                                         uint32_t b0, uint32_t b1) {
    asm volatile("mma.sync.aligned.m16n8k16.row.col.f32.bf16.bf16.f32 "
                 "{%0,%1,%2,%3}, {%4,%5,%6,%7}, {%8,%9}, {%0,%1,%2,%3};"
                 : "+f"(c[0]), "+f"(c[1]), "+f"(c[2]), "+f"(c[3])
                 : "r"(a[0]), "r"(a[1]), "r"(a[2]), "r"(a[3]), "r"(b0), "r"(b1));
}
__device__ __forceinline__ void cpa16(uint32_t saddr, const void* g) {
    asm volatile("cp.async.cg.shared.global [%0], [%1], 16;"
                 :: "r"(saddr), "l"(g) : "memory");
}
#define CPA_COMMIT() asm volatile("cp.async.commit_group;" ::: "memory")
#define CPA_WAIT(n)  asm volatile("cp.async.wait_group %0;" :: "n"(n) : "memory")

// ============ pipelined bf16-plane GEMM:  C[M,N] = A @ W^T ===================
// 128x128 tile, BK=32, 3-stage cp.async, XOR-swizzled 16-word rows, 2 CTA/SM.
// (exact R8 champion version)
#define BF_TILE_W  (128*16)
#define BF_STAGE_W (4*BF_TILE_W)
#define BF_SMEM    (3*BF_STAGE_W*4)  // 98304 B

template<int EP>
__global__ __launch_bounds__(256, 2) void gemm_bf(
    const __nv_bfloat16* __restrict__ Ah, const __nv_bfloat16* __restrict__ Al,
    const __nv_bfloat16* __restrict__ Wh, const __nv_bfloat16* __restrict__ Wl,
    float* __restrict__ C, int ldc, int K)
{
    extern __shared__ uint32_t sm[];
    const int t = threadIdx.x, lane = t & 31, warp = t >> 5;
    const int wm = warp >> 2, wn = warp & 3;
    const int m0 = blockIdx.y * 128, n0 = blockIdx.x * 128;
    const int nIt = K >> 5;
    const uint32_t base = (uint32_t)__cvta_generic_to_shared(&sm[0]);

    const int rA = ((lane >> 3) & 1) * 8 + (lane & 7);
    const int chA0 = (lane >> 4);
    const int rB = ((lane >> 4) & 1) * 8 + (lane & 7);
    const int chB0 = ((lane >> 3) & 1);

    float acc[4][4][4];
#pragma unroll
    for (int i = 0; i < 4; i++)
#pragma unroll
        for (int j = 0; j < 4; j++)
#pragma unroll
            for (int k = 0; k < 4; k++) acc[i][j][k] = 0.f;

    auto load_stage = [&](int s, int kb) {
        const uint32_t st = base + s * BF_STAGE_W * 4;
        const int koff = kb * 32;
#pragma unroll
        for (int i = 0; i < 8; i++) {
            const int c = t + i * 256;
            const int tile = c >> 9;
            const int w = c & 511;
            const int row = w >> 2;
            const int ch  = w & 3;
            const int chs = ch ^ ((row >> 1) & 3);
            const uint32_t sa = st + (tile * BF_TILE_W + row * 16 + chs * 4) * 4;
            const __nv_bfloat16* P = (tile == 0) ? Ah : (tile == 1) ? Al
                                   : (tile == 2) ? Wh : Wl;
            const int grow = ((tile < 2) ? m0 : n0) + row;
            cpa16(sa, P + (size_t)grow * K + koff + ch * 8);
        }
        CPA_COMMIT();
    };

    load_stage(0, 0);
    if (nIt > 1) load_stage(1, 1);

    for (int it = 0; it < nIt; ++it) {
        if (it + 2 < nIt) load_stage((it + 2) % 3, it + 2);
        if (it + 2 < nIt)      { CPA_WAIT(2); }
        else if (it + 1 < nIt) { CPA_WAIT(1); }
        else                   { CPA_WAIT(0); }
        __syncthreads();

        const uint32_t bAH = base + ((it % 3) * BF_STAGE_W) * 4;
        const uint32_t bAL = bAH + BF_TILE_W * 4;
        const uint32_t bBH = bAH + 2 * BF_TILE_W * 4;
        const uint32_t bBL = bAH + 3 * BF_TILE_W * 4;
#pragma unroll
        for (int kk = 0; kk < 2; ++kk) {
            uint32_t bh[2][4], bl[2][4];
            const int chB = kk * 2 + chB0;
#pragma unroll
            for (int np = 0; np < 2; ++np) {
                const int rowB = wn * 32 + np * 16 + rB;
                const uint32_t off = (rowB * 16 + ((chB ^ ((rowB >> 1) & 3)) * 4)) * 4;
                ldsm_x4(bh[np], bBH + off);
                ldsm_x4(bl[np], bBL + off);
            }
            const int chA = kk * 2 + chA0;
#pragma unroll
            for (int mt = 0; mt < 4; ++mt) {
                const int rowA = wm * 64 + mt * 16 + rA;
                const uint32_t off = (rowA * 16 + ((chA ^ ((rowA >> 1) & 3)) * 4)) * 4;
                uint32_t ah[4];
                ldsm_x4(ah, bAH + off);
#pragma unroll
                for (int nt = 0; nt < 4; ++nt) {
                    const int np = nt >> 1, e0 = (nt & 1) * 2, e1 = e0 + 1;
                    mma_bf16(acc[mt][nt], ah, bh[np][e0], bh[np][e1]);
                    mma_bf16(acc[mt][nt], ah, bl[np][e0], bl[np][e1]);
                }
                uint32_t al[4];
                ldsm_x4(al, bAL + off);
#pragma unroll
                for (int nt = 0; nt < 4; ++nt) {
                    const int np = nt >> 1, e0 = (nt & 1) * 2, e1 = e0 + 1;
                    mma_bf16(acc[mt][nt], al, bh[np][e0], bh[np][e1]);
                }
            }
        }
        __syncthreads();
    }

    const int er = lane >> 2;
    const int ec = (lane & 3) * 2;
#pragma unroll
    for (int mt = 0; mt < 4; ++mt) {
        const int r0 = m0 + wm * 64 + mt * 16 + er;
#pragma unroll
        for (int nt = 0; nt < 4; ++nt) {
            const int cc = n0 + wn * 32 + nt * 8 + ec;
            float v0 = acc[mt][nt][0], v1 = acc[mt][nt][1];
            float v2 = acc[mt][nt][2], v3 = acc[mt][nt][3];
            const size_t o0 = (size_t)r0 * ldc + cc;
            const size_t o1 = (size_t)(r0 + 8) * ldc + cc;
            if (EP == 2) {
                float2 q0 = *(const float2*)&C[o0];
                float2 q1 = *(const float2*)&C[o1];
                v0 += q0.x; v1 += q0.y; v2 += q1.x; v3 += q1.y;
            }
            float2 s;
            s.x = v0; s.y = v1; *(float2*)&C[o0] = s;
            s.x = v2; s.y = v3; *(float2*)&C[o1] = s;
        }
    }
}

// ====================== fp32-input mma.sync GEMM (small shapes) ==============
__device__ __forceinline__ void split_store_bf(uint32_t* hiP, uint32_t* loP, float4 v) {
    __nv_bfloat162 h0 = __floats2bfloat162_rn(v.x, v.y);
    __nv_bfloat162 h1 = __floats2bfloat162_rn(v.z, v.w);
    float lx = v.x - __bfloat162float(h0.x);
    float ly = v.y - __bfloat162float(h0.y);
    float lz = v.z - __bfloat162float(h1.x);
    float lw = v.w - __bfloat162float(h1.y);
    __nv_bfloat162 l0 = __floats2bfloat162_rn(lx, ly);
    __nv_bfloat162 l1 = __floats2bfloat162_rn(lz, lw);
    uint2 hu, lu;
    hu.x = *(uint32_t*)&h0; hu.y = *(uint32_t*)&h1;
    lu.x = *(uint32_t*)&l0; lu.y = *(uint32_t*)&l1;
    *(uint2*)hiP = hu;
    *(uint2*)loP = lu;
}

#define TILE_W   (128*20)
#define BUF_W    (4*TILE_W)
#define SMEM_BYT (2*BUF_W*4)   // 81920

// EP: 0 = none, 3 = +bias, 4 = +bias, softplus, write (dt, exp(-dt))
template<int EP>
__global__ __launch_bounds__(256) void gemm_tc(
    const float* __restrict__ A, int lda,
    const float* __restrict__ W,
    const float* __restrict__ bias,
    float* __restrict__ C, int ldc,
    int N, int K)
{
    extern __shared__ uint32_t sm[];

    const int t    = threadIdx.x;
    const int lane = t & 31, warp = t >> 5;
    const int wm   = warp >> 2, wn = warp & 3;
    const int m0   = blockIdx.y * 128, n0 = blockIdx.x * 128;

    const int sr = t >> 2;
    const int sc = (t & 3) * 4;

    const int rA = ((lane >> 3) & 1) * 8 + (lane & 7);
    const int cA = (lane >> 4) * 4;
    const int rB = ((lane >> 4) & 1) * 8 + (lane & 7);
    const int cB = ((lane >> 3) & 1) * 4;

    float acc[4][4][4];
#pragma unroll
    for (int i = 0; i < 4; i++)
#pragma unroll
        for (int j = 0; j < 4; j++)
#pragma unroll
            for (int k = 0; k < 4; k++) acc[i][j][k] = 0.f;

    const int nIt = K >> 5;
    const uint32_t base = (uint32_t)__cvta_generic_to_shared(&sm[0]);
    const int wc = sc >> 1;

    float4 a00, a01, a10, a11, b00, b01, b10, b11;
    {
        a00 = *(const float4*)&A[(size_t)(m0 + sr) * lda + sc];
        a01 = *(const float4*)&A[(size_t)(m0 + sr) * lda + sc + 16];
        a10 = *(const float4*)&A[(size_t)(m0 + sr + 64) * lda + sc];
        a11 = *(const float4*)&A[(size_t)(m0 + sr + 64) * lda + sc + 16];
        b00 = make_float4(0.f,0.f,0.f,0.f); b01 = b00; b10 = b00; b11 = b00;
        if (n0 + sr < N) {
            b00 = *(const float4*)&W[(size_t)(n0 + sr) * K + sc];
            b01 = *(const float4*)&W[(size_t)(n0 + sr) * K + sc + 16];
        }
        if (n0 + sr + 64 < N) {
            b10 = *(const float4*)&W[(size_t)(n0 + sr + 64) * K + sc];
            b11 = *(const float4*)&W[(size_t)(n0 + sr + 64) * K + sc + 16];
        }
        uint32_t* AH = sm;              uint32_t* AL = sm + TILE_W;
        uint32_t* BH = sm + 2 * TILE_W; uint32_t* BL = sm + 3 * TILE_W;
        split_store_bf(&AH[sr*20 + wc],            &AL[sr*20 + wc],            a00);
        split_store_bf(&AH[sr*20 + wc + 8],        &AL[sr*20 + wc + 8],        a01);
        split_store_bf(&AH[(sr+64)*20 + wc],       &AL[(sr+64)*20 + wc],       a10);
        split_store_bf(&AH[(sr+64)*20 + wc + 8],   &AL[(sr+64)*20 + wc + 8],   a11);
        split_store_bf(&BH[sr*20 + wc],            &BL[sr*20 + wc],            b00);
        split_store_bf(&BH[sr*20 + wc + 8],        &BL[sr*20 + wc + 8],        b01);
        split_store_bf(&BH[(sr+64)*20 + wc],       &BL[(sr+64)*20 + wc],       b10);
        split_store_bf(&BH[(sr+64)*20 + wc + 8],   &BL[(sr+64)*20 + wc + 8],   b11);
    }
    __syncthreads();

    for (int it = 0; it < nIt; ++it) {
        const int cur = it & 1;
        const bool more = (it + 1 < nIt);
        if (more) {
            int k0 = (it + 1) << 5;
            a00 = *(const float4*)&A[(size_t)(m0 + sr) * lda + k0 + sc];
            a01 = *(const float4*)&A[(size_t)(m0 + sr) * lda + k0 + sc + 16];
            a10 = *(const float4*)&A[(size_t)(m0 + sr + 64) * lda + k0 + sc];
            a11 = *(const float4*)&A[(size_t)(m0 + sr + 64) * lda + k0 + sc + 16];
            b00 = make_float4(0.f,0.f,0.f,0.f); b01 = b00; b10 = b00; b11 = b00;
            if (n0 + sr < N) {
                b00 = *(const float4*)&W[(size_t)(n0 + sr) * K + k0 + sc];
                b01 = *(const float4*)&W[(size_t)(n0 + sr) * K + k0 + sc + 16];
            }
            if (n0 + sr + 64 < N) {
                b10 = *(const float4*)&W[(size_t)(n0 + sr + 64) * K + k0 + sc];
                b11 = *(const float4*)&W[(size_t)(n0 + sr + 64) * K + k0 + sc + 16];
            }
        }

        const uint32_t bAH = base + (cur * BUF_W) * 4;
        const uint32_t bAL = bAH + TILE_W * 4;
        const uint32_t bBH = bAH + 2 * TILE_W * 4;
        const uint32_t bBL = bAH + 3 * TILE_W * 4;
#pragma unroll
        for (int kk = 0; kk < 2; ++kk) {
            uint32_t ah[4][4], al[4][4];
#pragma unroll
            for (int mt = 0; mt < 4; ++mt) {
                const uint32_t off = (((wm * 64 + mt * 16 + rA) * 20) + kk * 8 + cA) * 4;
                ldsm_x4(ah[mt], bAH + off);
                ldsm_x4(al[mt], bAL + off);
            }
            uint32_t bh[2][4], bl[2][4];
#pragma unroll
            for (int np = 0; np < 2; ++np) {
                const uint32_t off = (((wn * 32 + np * 16 + rB) * 20) + kk * 8 + cB) * 4;
                ldsm_x4(bh[np], bBH + off);
                ldsm_x4(bl[np], bBL + off);
            }
#pragma unroll
            for (int mt = 0; mt < 4; ++mt)
#pragma unroll
                for (int nt = 0; nt < 4; ++nt) {
                    const int np = nt >> 1, e0 = (nt & 1) * 2, e1 = e0 + 1;
                    mma_bf16(acc[mt][nt], ah[mt], bl[np][e0], bl[np][e1]);
                    mma_bf16(acc[mt][nt], al[mt], bh[np][e0], bh[np][e1]);
                    mma_bf16(acc[mt][nt], ah[mt], bh[np][e0], bh[np][e1]);
                }
        }

        if (more) {
            const int nxt = cur ^ 1;
            uint32_t* AH = sm + nxt * BUF_W; uint32_t* AL = AH + TILE_W;
            uint32_t* BH = AH + 2 * TILE_W;  uint32_t* BL = AH + 3 * TILE_W;
            split_store_bf(&AH[sr*20 + wc],          &AL[sr*20 + wc],          a00);
            split_store_bf(&AH[sr*20 + wc + 8],      &AL[sr*20 + wc + 8],      a01);
            split_store_bf(&AH[(sr+64)*20 + wc],     &AL[(sr+64)*20 + wc],     a10);
            split_store_bf(&AH[(sr+64)*20 + wc + 8], &AL[(sr+64)*20 + wc + 8], a11);
            split_store_bf(&BH[sr*20 + wc],          &BL[sr*20 + wc],          b00);
            split_store_bf(&BH[sr*20 + wc + 8],      &BL[sr*20 + wc + 8],      b01);
            split_store_bf(&BH[(sr+64)*20 + wc],     &BL[(sr+64)*20 + wc],     b10);
            split_store_bf(&BH[(sr+64)*20 + wc + 8], &BL[(sr+64)*20 + wc + 8], b11);
        }
        __syncthreads();
    }

    const int er = lane >> 2;
    const int ec = (lane & 3) * 2;
#pragma unroll
    for (int mt = 0; mt < 4; ++mt) {
        const int r0 = m0 + wm * 64 + mt * 16 + er;
#pragma unroll
        for (int nt = 0; nt < 4; ++nt) {
            const int cc = n0 + wn * 32 + nt * 8 + ec;
            if (cc >= N) continue;
            float v0 = acc[mt][nt][0], v1 = acc[mt][nt][1];
            float v2 = acc[mt][nt][2], v3 = acc[mt][nt][3];
            if (EP == 4) {
                const float bb0 = bias[cc], bb1 = bias[cc + 1];
                float vv[4] = {v0 + bb0, v1 + bb1, v2 + bb0, v3 + bb1};
                float dt[4], pp[4];
#pragma unroll
                for (int i = 0; i < 4; i++) {
                    float v = vv[i];
                    float e = __expf(-fabsf(v));
                    dt[i] = fmaxf(v, 0.f) + __logf(1.f + e);
                    pp[i] = __fdividef((v > 0.f ? e : 1.f), 1.f + e);
                }
                float4 o;
                o.x = dt[0]; o.y = pp[0]; o.z = dt[1]; o.w = pp[1];
                *(float4*)&C[2 * ((size_t)r0 * ldc + cc)] = o;
                o.x = dt[2]; o.y = pp[2]; o.z = dt[3]; o.w = pp[3];
                *(float4*)&C[2 * ((size_t)(r0 + 8) * ldc + cc)] = o;
            } else {
                if (EP == 3) {
                    const float bb0 = bias[cc], bb1 = bias[cc + 1];
                    v0 += bb0; v1 += bb1; v2 += bb0; v3 += bb1;
                }
                const size_t o0 = (size_t)r0 * ldc + cc;
                const size_t o1 = (size_t)(r0 + 8) * ldc + cc;
                float2 s;
                s.x = v0; s.y = v1; *(float2*)&C[o0] = s;
                s.x = v2; s.y = v3; *(float2*)&C[o1] = s;
            }
        }
    }
}

// ---------------- transposes -------------------------------------------------
__global__ void transpose_in_k(const float* __restrict__ in, float* __restrict__ inT)
{
    __shared__ float tile[32][33];
    int b  = blockIdx.z;
    int n0 = blockIdx.y * 32;
    int l0 = blockIdx.x * 32;
    int tx = threadIdx.x, ty = threadIdx.y;
    for (int i = ty; i < 32; i += 8)
        tile[i][tx] = in[(size_t)b * NUML * SEQ + (size_t)(n0 + i) * SEQ + l0 + tx];
    __syncthreads();
    for (int i = ty; i < 32; i += 8)
        inT[(size_t)(b * SEQ + l0 + i) * NUML + n0 + tx] = tile[tx][i];
}
__global__ void transpose_out_k(const float* __restrict__ Ct, float* __restrict__ out)
{
    __shared__ float tile[32][33];
    int b  = blockIdx.z;
    int l0 = blockIdx.x * 32;
    int p0 = blockIdx.y * 32;
    int tx = threadIdx.x, ty = threadIdx.y;
    for (int i = ty; i < 32; i += 8)
        tile[i][tx] = Ct[(size_t)(b * SEQ + l0 + i) * PREDL + p0 + tx];
    __syncthreads();
    for (int i = ty; i < 32; i += 8)
        out[(size_t)b * PREDL * SEQ + (size_t)(p0 + i) * SEQ + l0 + tx] = tile[tx][i];
}

// ---------------- depthwise conv + silu, 4 t-rows per thread ------------------
__global__ void conv_silu_k(const float* __restrict__ xz, const float* __restrict__ cw,
                            const float* __restrict__ cb, float* __restrict__ xc, int rev)
{
    const int i = blockIdx.x * blockDim.x + threadIdx.x;
    const int d4 = (i & 255) * 4;
    const int g  = i >> 8;
    const int t0 = (g & 255) * 4;
    const int b  = g >> 8;

    float4 w[4];
    w[0] = *(const float4*)&cw[(d4 + 0) * 4];
    w[1] = *(const float4*)&cw[(d4 + 1) * 4];
    w[2] = *(const float4*)&cw[(d4 + 2) * 4];
    w[3] = *(const float4*)&cw[(d4 + 3) * 4];
    const float4 bias = *(const float4*)&cb[d4];
    float4 out[4] = {bias, bias, bias, bias};

    const int jlo = rev ? 0 : -3;
#pragma unroll
    for (int jj = 0; jj < 7; jj++) {
        const int tt = t0 + jlo + jj;
        if ((unsigned)tt >= SEQ) continue;
        const float4 v = *(const float4*)&xz[(size_t)(b * SEQ + tt) * (2 * DINNER) + d4];
#pragma unroll
        for (int o = 0; o < 4; o++) {
            const int m = jj - o;
            if (m < 0 || m > 3) continue;
            const int k = rev ? (3 - m) : m;
            out[o].x = fmaf((&w[0].x)[k], v.x, out[o].x);
            out[o].y = fmaf((&w[1].x)[k], v.y, out[o].y);
            out[o].z = fmaf((&w[2].x)[k], v.z, out[o].z);
            out[o].w = fmaf((&w[3].x)[k], v.w, out[o].w);
        }
    }
#pragma unroll
    for (int o = 0; o < 4; o++) {
        float4 r = out[o];
        r.x = silu_f(r.x); r.y = silu_f(r.y);
        r.z = silu_f(r.z); r.w = silu_f(r.w);
        *(float4*)&xc[(size_t)(b * SEQ + t0 + o) * DINNER + d4] = r;
    }
}

// ---------------- selective scan, 4 lanes per (b,d), 4-deep prefetch ----------
__global__ void scan_k(const float2* __restrict__ dtp, const float* __restrict__ xcp,
                       const float* __restrict__ xdbl, const float* __restrict__ xz,
                       const float* __restrict__ a_log, const float* __restrict__ d_skip,
                       __nv_bfloat16* __restrict__ ysh, __nv_bfloat16* __restrict__ ysl,
                       int rev)
{
    int idx = blockIdx.x * blockDim.x + threadIdx.x;
    int q   = idx & 3;
    int gid = idx >> 2;
    int d = gid & (DINNER - 1);
    int b = gid >> 10;

    float A0 = -__expf(a_log[d * DSTATE + 4 * q + 0]);
    float A1 = -__expf(a_log[d * DSTATE + 4 * q + 1]);
    float A2 = -__expf(a_log[d * DSTATE + 4 * q + 2]);
    float A3 = -__expf(a_log[d * DSTATE + 4 * q + 3]);
    bool fast = fabsf(A0 + (4 * q + 1)) < 1e-4f && fabsf(A1 + (4 * q + 2)) < 1e-4f &&
                fabsf(A2 + (4 * q + 3)) < 1e-4f && fabsf(A3 + (4 * q + 4)) < 1e-4f;
    fast = __all_sync(0xffffffffu, fast);

    float h0 = 0.f, h1 = 0.f, h2 = 0.f, h3 = 0.f;
    const float Dp = d_skip[d];

    float2 dpb[4]; float xb[4]; float4 Bb[4], Cb[4]; float zb[4];
#pragma unroll
    for (int j = 0; j < 4; j++) {
        const int tt = rev ? (SEQ - 1 - j) : j;
        const size_t r = (size_t)b * SEQ + tt;
        dpb[j] = dtp[r * DINNER + d];
        xb[j]  = xcp[r * DINNER + d];
        Bb[j]  = *(const float4*)&xdbl[r * 64 + 32 + 4 * q];
        Cb[j]  = *(const float4*)&xdbl[r * 64 + 48 + 4 * q];
        zb[j]  = xz[r * (2 * DINNER) + DINNER + d];
    }

#pragma unroll 4
    for (int step = 0; step < SEQ; ++step) {
        const int j = step & 3;
        const int tc = rev ? (SEQ - 1 - step) : step;
        const size_t rc = (size_t)b * SEQ + tc;
        const float2 dpc = dpb[j];
        const float  xc_ = xb[j];
        const float4 Bc = Bb[j], Cc = Cb[j];
        const float  zc = zb[j];

        if (step + 4 < SEQ) {
            const int tn = rev ? (SEQ - 5 - step) : (step + 4);
            const size_t rn = (size_t)b * SEQ + tn;
            dpb[j] = dtp[rn * DINNER + d];
            xb[j]  = xcp[rn * DINNER + d];
            Bb[j]  = *(const float4*)&xdbl[rn * 64 + 32 + 4 * q];
            Cb[j]  = *(const float4*)&xdbl[rn * 64 + 48 + 4 * q];
            zb[j]  = xz[rn * (2 * DINNER) + DINNER + d];
        }

        const float dtx = dpc.x * xc_;
        float dA0, dA1, dA2, dA3;
        if (fast) {
            const float p  = dpc.y;
            const float p2 = p * p, p4 = p2 * p2, p8 = p4 * p4;
            float m = 1.f;
            if (q & 1) m = p4;
            if (q & 2) m *= p8;
            dA0 = m * p; dA1 = dA0 * p; dA2 = dA1 * p; dA3 = dA2 * p;
        } else {
            dA0 = __expf(dpc.x * A0); dA1 = __expf(dpc.x * A1);
            dA2 = __expf(dpc.x * A2); dA3 = __expf(dpc.x * A3);
        }
        h0 = fmaf(dA0, h0, dtx * Bc.x);
        h1 = fmaf(dA1, h1, dtx * Bc.y);
        h2 = fmaf(dA2, h2, dtx * Bc.z);
        h3 = fmaf(dA3, h3, dtx * Bc.w);
        float yp = (h0 * Cc.x + h1 * Cc.y) + (h2 * Cc.z + h3 * Cc.w);
        yp += __shfl_xor_sync(0xffffffffu, yp, 1);
        yp += __shfl_xor_sync(0xffffffffu, yp, 2);
        if (q == 0) {
            const float yv = (yp + xc_ * Dp) * silu_f(zc);
            const __nv_bfloat16 hb = __float2bfloat16_rn(yv);
            ysh[rc * DINNER + d] = hb;
            ysl[rc * DINNER + d] = __float2bfloat16_rn(yv - __bfloat162float(hb));
        }
    }
}

// ---------------- silu(a + a2) + dual-bf16 plane emit --------------------------
__global__ void silu3_k(const float4* __restrict__ a, const float4* __restrict__ a2,
                        float4* __restrict__ o,
                        __nv_bfloat16* __restrict__ h, __nv_bfloat16* __restrict__ l, int n4)
{
    int i = blockIdx.x * blockDim.x + threadIdx.x;
    if (i >= n4) return;
    float4 v = a[i];
    const float4 w = a2[i];
    v.x = silu_f(v.x + w.x); v.y = silu_f(v.y + w.y);
    v.z = silu_f(v.z + w.z); v.w = silu_f(v.w + w.w);
    o[i] = v;
    __nv_bfloat162 h0 = __floats2bfloat162_rn(v.x, v.y);
    __nv_bfloat162 h1 = __floats2bfloat162_rn(v.z, v.w);
    __nv_bfloat162 l0 = __floats2bfloat162_rn(v.x - __bfloat162float(h0.x),
                                              v.y - __bfloat162float(h0.y));
    __nv_bfloat162 l1 = __floats2bfloat162_rn(v.z - __bfloat162float(h1.x),
                                              v.w - __bfloat162float(h1.y));
    ((__nv_bfloat162*)h)[i * 2]     = h0;
    ((__nv_bfloat162*)h)[i * 2 + 1] = h1;
    ((__nv_bfloat162*)l)[i * 2]     = l0;
    ((__nv_bfloat162*)l)[i * 2 + 1] = l1;
}

// ---------------- fp32 -> bf16 hi/lo split ------------------------------------
__global__ void split_k(const float* __restrict__ a, __nv_bfloat16* __restrict__ h,
                        __nv_bfloat16* __restrict__ l, int n)
{
    int i = blockIdx.x * blockDim.x + threadIdx.x;
    if (i >= n) return;
    const float v = a[i];
    const __nv_bfloat16 hb = __float2bfloat16_rn(v);
    h[i] = hb;
    l[i] = __float2bfloat16_rn(v - __bfloat162float(hb));
}

// ---------------- launcher ---------------------------------------------------
extern "C" void kernel_launch(void* const* d_in, const int* in_sizes, int n_in,
                              void* d_out, int out_size)
{
    (void)in_sizes; (void)n_in; (void)out_size;
    const float* inputs = (const float*)d_in[0];
    const float* w1     = (const float*)d_in[1];
    const float* b1     = (const float*)d_in[2];
    const float* w_in   = (const float*)d_in[3];
    const float* conv_w = (const float*)d_in[4];
    const float* conv_b = (const float*)d_in[5];
    const float* w_xp   = (const float*)d_in[6];
    const float* w_dt   = (const float*)d_in[7];
    const float* b_dt   = (const float*)d_in[8];
    const float* a_log  = (const float*)d_in[9];
    const float* d_skip = (const float*)d_in[10];
    const float* w_out  = (const float*)d_in[11];
    const float* w2     = (const float*)d_in[12];
    const float* b2     = (const float*)d_in[13];

    float *inT, *emb, *acc, *acc2, *xzA, *xzB, *xcA, *xcB, *xdA, *xdB, *dtA, *dtB;
    __nv_bfloat16 *embh, *embl, *yshA, *yslA, *yshB, *yslB, *winh, *winl, *wouth, *woutl;
    cudaGetSymbolAddress((void**)&inT,   g_inT);
    cudaGetSymbolAddress((void**)&emb,   g_emb);
    cudaGetSymbolAddress((void**)&acc,   g_acc);
    cudaGetSymbolAddress((void**)&acc2,  g_acc2);
    cudaGetSymbolAddress((void**)&xzA,   g_xz);
    cudaGetSymbolAddress((void**)&xzB,   g_xz2);
    cudaGetSymbolAddress((void**)&xcA,   g_xc);
    cudaGetSymbolAddress((void**)&xcB,   g_xc2);
    cudaGetSymbolAddress((void**)&xdA,   g_xdbl);
    cudaGetSymbolAddress((void**)&xdB,   g_xdbl2);
    cudaGetSymbolAddress((void**)&dtA,   g_dtp);
    cudaGetSymbolAddress((void**)&dtB,   g_dtp2);
    cudaGetSymbolAddress((void**)&embh,  g_embh);
    cudaGetSymbolAddress((void**)&embl,  g_embl);
    cudaGetSymbolAddress((void**)&yshA,  g_ysh);
    cudaGetSymbolAddress((void**)&yslA,  g_ysl);
    cudaGetSymbolAddress((void**)&yshB,  g_ysh2);
    cudaGetSymbolAddress((void**)&yslB,  g_ysl2);
    cudaGetSymbolAddress((void**)&winh,  g_winh);
    cudaGetSymbolAddress((void**)&winl,  g_winl);
    cudaGetSymbolAddress((void**)&wouth, g_wouth);
    cudaGetSymbolAddress((void**)&woutl, g_woutl);

    cudaFuncSetAttribute(gemm_tc<0>, cudaFuncAttributeMaxDynamicSharedMemorySize, SMEM_BYT);
    cudaFuncSetAttribute(gemm_tc<3>, cudaFuncAttributeMaxDynamicSharedMemorySize, SMEM_BYT);
    cudaFuncSetAttribute(gemm_tc<4>, cudaFuncAttributeMaxDynamicSharedMemorySize, SMEM_BYT);
    cudaFuncSetAttribute(gemm_bf<0>, cudaFuncAttributeMaxDynamicSharedMemorySize, BF_SMEM);

    // streams + events (created once; no device memory)
    static cudaStream_t sx[4] = {0, 0, 0, 0};   // sx[0] = default stream
    static cudaEvent_t evF[2], evJ[2][3], evS, evW;
    if (!sx[1]) {
        for (int i = 1; i < 4; i++)
            cudaStreamCreateWithFlags(&sx[i], cudaStreamNonBlocking);
        for (int i = 0; i < 2; i++) {
            cudaEventCreateWithFlags(&evF[i], cudaEventDisableTiming);
            for (int j = 0; j < 3; j++)
                cudaEventCreateWithFlags(&evJ[i][j], cudaEventDisableTiming);
        }
        cudaEventCreateWithFlags(&evS, cudaEventDisableTiming);
        cudaEventCreateWithFlags(&evW, cudaEventDisableTiming);
    }

    dim3 tb(32, 8);

    // fork: weight splits on sx[1], overlapped with the embedding chain
    cudaEventRecord(evS, 0);
    cudaStreamWaitEvent(sx[1], evS, 0);
    split_k<<<(4*2*DINNER*DMODEL + 255)/256, 256, 0, sx[1]>>>(
        w_in,  winh,  winl,  4*2*DINNER*DMODEL);
    split_k<<<(4*DMODEL*DINNER  + 255)/256, 256, 0, sx[1]>>>(
        w_out, wouth, woutl, 4*DMODEL*DINNER);
    cudaEventRecord(evW, sx[1]);

    transpose_in_k<<<dim3(SEQ / 32, NUML / 32, BATCH), tb>>>(inputs, inT);
    gemm_tc<3><<<dim3(DMODEL / 128, MROWS / 128), 256, SMEM_BYT>>>(
        inT, NUML, w1, b1, emb, DMODEL, DMODEL, NUML);
    split_k<<<(MROWS*DMODEL + 255)/256, 256>>>(emb, embh, embl, MROWS*DMODEL);

    cudaStreamWaitEvent(0, evW, 0);   // stream0 now ordered after weight splits

    for (int layer = 0; layer < 2; ++layer) {
        cudaEventRecord(evF[layer], 0);
        for (int i = 1; i < 4; i++)
            cudaStreamWaitEvent(sx[i], evF[layer], 0);

        for (int chain = 0; chain < 4; ++chain) {
            const int dir  = chain >> 1;
            const int half = chain & 1;
            const int off = dir * 2 + layer;
            cudaStream_t st = sx[chain];
            const size_t R = (size_t)half * MHALF;

            float* xz  = (dir ? xzB : xzA) + R * 2 * DINNER;
            float* xc  = (dir ? xcB : xcA) + R * DINNER;
            float* xd  = (dir ? xdB : xdA) + R * 64;
            float* dtp = (dir ? dtB : dtA) + R * DINNER * 2;
            __nv_bfloat16* ysh = (dir ? yshB : yshA) + R * DINNER;
            __nv_bfloat16* ysl = (dir ? yslB : yslA) + R * DINNER;
            float* accD = (dir ? acc2 : acc) + R * DMODEL;
            const __nv_bfloat16* Ah = embh + R * DMODEL;
            const __nv_bfloat16* Al = embl + R * DMODEL;

            const __nv_bfloat16* Winh = winh + (size_t)off * 2 * DINNER * DMODEL;
            const __nv_bfloat16* Winl = winl + (size_t)off * 2 * DINNER * DMODEL;
            const __nv_bfloat16* Wouh = wouth + (size_t)off * DMODEL * DINNER;
            const __nv_bfloat16* Woul = woutl + (size_t)off * DMODEL * DINNER;
            const float* cw   = conv_w + (size_t)off * DINNER * 4;
            const float* cb   = conv_b + (size_t)off * DINNER;
            const float* Wxp  = w_xp   + (size_t)off * 64 * DINNER;
            const float* Wdt  = w_dt   + (size_t)off * DINNER * DTRANK;
            const float* bdt  = b_dt   + (size_t)off * DINNER;
            const float* Al_  = a_log  + (size_t)off * DINNER * DSTATE;
            const float* Dp   = d_skip + (size_t)off * DINNER;

            gemm_bf<0><<<dim3(2 * DINNER / 128, MHALF / 128), 256, BF_SMEM, st>>>(
                Ah, Al, Winh, Winl, xz, 2 * DINNER, DMODEL);

            conv_silu_k<<<(MHALF / 4) * (DINNER / 4) / 256, 256, 0, st>>>(
                xz, cw, cb, xc, dir);

            gemm_tc<0><<<dim3(1, MHALF / 128), 256, SMEM_BYT, st>>>(
                xc, DINNER, Wxp, nullptr, xd, 64, 64, DINNER);

            gemm_tc<4><<<dim3(DINNER / 128, MHALF / 128), 256, SMEM_BYT, st>>>(
                xd, 64, Wdt, bdt, dtp, DINNER, DINNER, DTRANK);

            scan_k<<<((BATCH / 2) * DINNER * 4) / 256, 256, 0, st>>>(
                (const float2*)dtp, xc, xd, xz, Al_, Dp, ysh, ysl, dir);

            gemm_bf<0><<<dim3(DMODEL / 128, MHALF / 128), 256, BF_SMEM, st>>>(
                ysh, ysl, Wouh, Woul, accD, DMODEL, DINNER);
        }

        for (int i = 1; i < 4; i++) {
            cudaEventRecord(evJ[layer][i - 1], sx[i]);
            cudaStreamWaitEvent(0, evJ[layer][i - 1], 0);
        }

        silu3_k<<<(MROWS * DMODEL / 4 + 255) / 256, 256>>>(
            (const float4*)acc, (const float4*)acc2, (float4*)emb, embh, embl,
            MROWS * DMODEL / 4);
    }

    gemm_tc<3><<<dim3(2, MROWS / 128), 256, SMEM_BYT>>>(
        emb, DMODEL, w2, b2, acc, PREDL, PREDL, DMODEL);

    transpose_out_k<<<dim3(SEQ / 32, PREDL / 32, BATCH), tb>>>(acc, (float*)d_out);
}

// round 15
// speedup vs baseline: 1.0133x; 1.0133x over previous
#include <cuda_runtime.h>
#include <cuda_bf16.h>
#include <math.h>
#include <stdint.h>

#define BATCH  16
#define SEQ    1024
#define DMODEL 512
#define DINNER 1024
#define DTRANK 32
#define DSTATE 16
#define PREDL  192
#define NUML   96
#define MROWS  (BATCH*SEQ)   // 16384

// ---------------- scratch (device globals; no allocations allowed) ----------
__device__ float g_inT [MROWS*NUML];
__device__ float g_emb [MROWS*DMODEL];
__device__ float g_acc [MROWS*DMODEL];
__device__ float g_acc2[MROWS*DMODEL];
__device__ float g_xz  [MROWS*2*DINNER];
__device__ float g_xz2 [MROWS*2*DINNER];
__device__ float g_xc  [MROWS*DINNER];
__device__ float g_xc2 [MROWS*DINNER];
__device__ float g_xdbl [MROWS*64];
__device__ float g_xdbl2[MROWS*64];
__device__ float g_dtp [MROWS*DINNER*2];   // interleaved (dt, exp(-dt))
__device__ float g_dtp2[MROWS*DINNER*2];
__device__ __nv_bfloat16 g_embh[MROWS*DMODEL];
__device__ __nv_bfloat16 g_embl[MROWS*DMODEL];
__device__ __nv_bfloat16 g_ysh [MROWS*DINNER];
__device__ __nv_bfloat16 g_ysl [MROWS*DINNER];
__device__ __nv_bfloat16 g_ysh2[MROWS*DINNER];
__device__ __nv_bfloat16 g_ysl2[MROWS*DINNER];
__device__ __nv_bfloat16 g_winh[4*2*DINNER*DMODEL];
__device__ __nv_bfloat16 g_winl[4*2*DINNER*DMODEL];
__device__ __nv_bfloat16 g_wouth[4*DMODEL*DINNER];
__device__ __nv_bfloat16 g_woutl[4*DMODEL*DINNER];

__device__ __forceinline__ float silu_f(float x) {
    return x * (1.f / (1.f + __expf(-x)));
}

__device__ __forceinline__ void ldsm_x4(uint32_t (&r)[4], uint32_t addr) {
    asm volatile("ldmatrix.sync.aligned.m8n8.x4.shared.b16 {%0,%1,%2,%3}, [%4];"
                 : "=r"(r[0]), "=r"(r[1]), "=r"(r[2]), "=r"(r[3]) : "r"(addr));
}
__device__ __forceinline__ void mma_bf16(float (&c)[4], const uint32_t (&a)[4],
                                         uint32_t b0, uint32_t b1) {
    asm volatile("mma.sync.aligned.m16n8k16.row.col.f32.bf16.bf16.f32 "
                 "{%0,%1,%2,%3}, {%4,%5,%6,%7}, {%8,%9}, {%0,%1,%2,%3};"
                 : "+f"(c[0]), "+f"(c[1]), "+f"(c[2]), "+f"(c[3])
                 : "r"(a[0]), "r"(a[1]), "r"(a[2]), "r"(a[3]), "r"(b0), "r"(b1));
}
__device__ __forceinline__ void cpa16(uint32_t saddr, const void* g) {
    asm volatile("cp.async.cg.shared.global [%0], [%1], 16;"
                 :: "r"(saddr), "l"(g) : "memory");
}
#define CPA_COMMIT() asm volatile("cp.async.commit_group;" ::: "memory")
#define CPA_WAIT(n)  asm volatile("cp.async.wait_group %0;" :: "n"(n) : "memory")

// ============ pipelined bf16-plane GEMM:  C[M,N] = A @ W^T ===================
// 128x128 tile, BK=32, 3-stage cp.async, XOR-swizzled 16-word rows, 2 CTA/SM.
// (exact R8/R13 champion version)
#define BF_TILE_W  (128*16)
#define BF_STAGE_W (4*BF_TILE_W)
#define BF_SMEM    (3*BF_STAGE_W*4)  // 98304 B

template<int EP>
__global__ __launch_bounds__(256, 2) void gemm_bf(
    const __nv_bfloat16* __restrict__ Ah, const __nv_bfloat16* __restrict__ Al,
    const __nv_bfloat16* __restrict__ Wh, const __nv_bfloat16* __restrict__ Wl,
    float* __restrict__ C, int ldc, int K)
{
    extern __shared__ uint32_t sm[];
    const int t = threadIdx.x, lane = t & 31, warp = t >> 5;
    const int wm = warp >> 2, wn = warp & 3;
    const int m0 = blockIdx.y * 128, n0 = blockIdx.x * 128;
    const int nIt = K >> 5;
    const uint32_t base = (uint32_t)__cvta_generic_to_shared(&sm[0]);

    const int rA = ((lane >> 3) & 1) * 8 + (lane & 7);
    const int chA0 = (lane >> 4);
    const int rB = ((lane >> 4) & 1) * 8 + (lane & 7);
    const int chB0 = ((lane >> 3) & 1);

    float acc[4][4][4];
#pragma unroll
    for (int i = 0; i < 4; i++)
#pragma unroll
        for (int j = 0; j < 4; j++)
#pragma unroll
            for (int k = 0; k < 4; k++) acc[i][j][k] = 0.f;

    auto load_stage = [&](int s, int kb) {
        const uint32_t st = base + s * BF_STAGE_W * 4;
        const int koff = kb * 32;
#pragma unroll
        for (int i = 0; i < 8; i++) {
            const int c = t + i * 256;
            const int tile = c >> 9;
            const int w = c & 511;
            const int row = w >> 2;
            const int ch  = w & 3;
            const int chs = ch ^ ((row >> 1) & 3);
            const uint32_t sa = st + (tile * BF_TILE_W + row * 16 + chs * 4) * 4;
            const __nv_bfloat16* P = (tile == 0) ? Ah : (tile == 1) ? Al
                                   : (tile == 2) ? Wh : Wl;
            const int grow = ((tile < 2) ? m0 : n0) + row;
            cpa16(sa, P + (size_t)grow * K + koff + ch * 8);
        }
        CPA_COMMIT();
    };

    load_stage(0, 0);
    if (nIt > 1) load_stage(1, 1);

    for (int it = 0; it < nIt; ++it) {
        if (it + 2 < nIt) load_stage((it + 2) % 3, it + 2);
        if (it + 2 < nIt)      { CPA_WAIT(2); }
        else if (it + 1 < nIt) { CPA_WAIT(1); }
        else                   { CPA_WAIT(0); }
        __syncthreads();

        const uint32_t bAH = base + ((it % 3) * BF_STAGE_W) * 4;
        const uint32_t bAL = bAH + BF_TILE_W * 4;
        const uint32_t bBH = bAH + 2 * BF_TILE_W * 4;
        const uint32_t bBL = bAH + 3 * BF_TILE_W * 4;
#pragma unroll
        for (int kk = 0; kk < 2; ++kk) {
            uint32_t bh[2][4], bl[2][4];
            const int chB = kk * 2 + chB0;
#pragma unroll
            for (int np = 0; np < 2; ++np) {
                const int rowB = wn * 32 + np * 16 + rB;
                const uint32_t off = (rowB * 16 + ((chB ^ ((rowB >> 1) & 3)) * 4)) * 4;
                ldsm_x4(bh[np], bBH + off);
                ldsm_x4(bl[np], bBL + off);
            }
            const int chA = kk * 2 + chA0;
#pragma unroll
            for (int mt = 0; mt < 4; ++mt) {
                const int rowA = wm * 64 + mt * 16 + rA;
                const uint32_t off = (rowA * 16 + ((chA ^ ((rowA >> 1) & 3)) * 4)) * 4;
                uint32_t ah[4];
                ldsm_x4(ah, bAH + off);
#pragma unroll
                for (int nt = 0; nt < 4; ++nt) {
                    const int np = nt >> 1, e0 = (nt & 1) * 2, e1 = e0 + 1;
                    mma_bf16(acc[mt][nt], ah, bh[np][e0], bh[np][e1]);
                    mma_bf16(acc[mt][nt], ah, bl[np][e0], bl[np][e1]);
                }
                uint32_t al[4];
                ldsm_x4(al, bAL + off);
#pragma unroll
                for (int nt = 0; nt < 4; ++nt) {
                    const int np = nt >> 1, e0 = (nt & 1) * 2, e1 = e0 + 1;
                    mma_bf16(acc[mt][nt], al, bh[np][e0], bh[np][e1]);
                }
            }
        }
        __syncthreads();
    }

    const int er = lane >> 2;
    const int ec = (lane & 3) * 2;
#pragma unroll
    for (int mt = 0; mt < 4; ++mt) {
        const int r0 = m0 + wm * 64 + mt * 16 + er;
#pragma unroll
        for (int nt = 0; nt < 4; ++nt) {
            const int cc = n0 + wn * 32 + nt * 8 + ec;
            float v0 = acc[mt][nt][0], v1 = acc[mt][nt][1];
            float v2 = acc[mt][nt][2], v3 = acc[mt][nt][3];
            const size_t o0 = (size_t)r0 * ldc + cc;
            const size_t o1 = (size_t)(r0 + 8) * ldc + cc;
            if (EP == 2) {
                float2 q0 = *(const float2*)&C[o0];
                float2 q1 = *(const float2*)&C[o1];
                v0 += q0.x; v1 += q0.y; v2 += q1.x; v3 += q1.y;
            }
            float2 s;
            s.x = v0; s.y = v1; *(float2*)&C[o0] = s;
            s.x = v2; s.y = v3; *(float2*)&C[o1] = s;
        }
    }
}

// ====================== fp32-input mma.sync GEMM (small shapes) ==============
__device__ __forceinline__ void split_store_bf(uint32_t* hiP, uint32_t* loP, float4 v) {
    __nv_bfloat162 h0 = __floats2bfloat162_rn(v.x, v.y);
    __nv_bfloat162 h1 = __floats2bfloat162_rn(v.z, v.w);
    float lx = v.x - __bfloat162float(h0.x);
    float ly = v.y - __bfloat162float(h0.y);
    float lz = v.z - __bfloat162float(h1.x);
    float lw = v.w - __bfloat162float(h1.y);
    __nv_bfloat162 l0 = __floats2bfloat162_rn(lx, ly);
    __nv_bfloat162 l1 = __floats2bfloat162_rn(lz, lw);
    uint2 hu, lu;
    hu.x = *(uint32_t*)&h0; hu.y = *(uint32_t*)&h1;
    lu.x = *(uint32_t*)&l0; lu.y = *(uint32_t*)&l1;
    *(uint2*)hiP = hu;
    *(uint2*)loP = lu;
}

#define TILE_W   (128*20)
#define BUF_W    (4*TILE_W)
#define SMEM_BYT (2*BUF_W*4)   // 81920

// EP: 0 = none, 3 = +bias, 4 = +bias, softplus, write (dt, exp(-dt))
template<int EP>
__global__ __launch_bounds__(256) void gemm_tc(
    const float* __restrict__ A, int lda,
    const float* __restrict__ W,
    const float* __restrict__ bias,
    float* __restrict__ C, int ldc,
    int N, int K)
{
    extern __shared__ uint32_t sm[];

    const int t    = threadIdx.x;
    const int lane = t & 31, warp = t >> 5;
    const int wm   = warp >> 2, wn = warp & 3;
    const int m0   = blockIdx.y * 128, n0 = blockIdx.x * 128;

    const int sr = t >> 2;
    const int sc = (t & 3) * 4;

    const int rA = ((lane >> 3) & 1) * 8 + (lane & 7);
    const int cA = (lane >> 4) * 4;
    const int rB = ((lane >> 4) & 1) * 8 + (lane & 7);
    const int cB = ((lane >> 3) & 1) * 4;

    float acc[4][4][4];
#pragma unroll
    for (int i = 0; i < 4; i++)
#pragma unroll
        for (int j = 0; j < 4; j++)
#pragma unroll
            for (int k = 0; k < 4; k++) acc[i][j][k] = 0.f;

    const int nIt = K >> 5;
    const uint32_t base = (uint32_t)__cvta_generic_to_shared(&sm[0]);
    const int wc = sc >> 1;

    float4 a00, a01, a10, a11, b00, b01, b10, b11;
    {
        a00 = *(const float4*)&A[(size_t)(m0 + sr) * lda + sc];
        a01 = *(const float4*)&A[(size_t)(m0 + sr) * lda + sc + 16];
        a10 = *(const float4*)&A[(size_t)(m0 + sr + 64) * lda + sc];
        a11 = *(const float4*)&A[(size_t)(m0 + sr + 64) * lda + sc + 16];
        b00 = make_float4(0.f,0.f,0.f,0.f); b01 = b00; b10 = b00; b11 = b00;
        if (n0 + sr < N) {
            b00 = *(const float4*)&W[(size_t)(n0 + sr) * K + sc];
            b01 = *(const float4*)&W[(size_t)(n0 + sr) * K + sc + 16];
        }
        if (n0 + sr + 64 < N) {
            b10 = *(const float4*)&W[(size_t)(n0 + sr + 64) * K + sc];
            b11 = *(const float4*)&W[(size_t)(n0 + sr + 64) * K + sc + 16];
        }
        uint32_t* AH = sm;              uint32_t* AL = sm + TILE_W;
        uint32_t* BH = sm + 2 * TILE_W; uint32_t* BL = sm + 3 * TILE_W;
        split_store_bf(&AH[sr*20 + wc],            &AL[sr*20 + wc],            a00);
        split_store_bf(&AH[sr*20 + wc + 8],        &AL[sr*20 + wc + 8],        a01);
        split_store_bf(&AH[(sr+64)*20 + wc],       &AL[(sr+64)*20 + wc],       a10);
        split_store_bf(&AH[(sr+64)*20 + wc + 8],   &AL[(sr+64)*20 + wc + 8],   a11);
        split_store_bf(&BH[sr*20 + wc],            &BL[sr*20 + wc],            b00);
        split_store_bf(&BH[sr*20 + wc + 8],        &BL[sr*20 + wc + 8],        b01);
        split_store_bf(&BH[(sr+64)*20 + wc],       &BL[(sr+64)*20 + wc],       b10);
        split_store_bf(&BH[(sr+64)*20 + wc + 8],   &BL[(sr+64)*20 + wc + 8],   b11);
    }
    __syncthreads();

    for (int it = 0; it < nIt; ++it) {
        const int cur = it & 1;
        const bool more = (it + 1 < nIt);
        if (more) {
            int k0 = (it + 1) << 5;
            a00 = *(const float4*)&A[(size_t)(m0 + sr) * lda + k0 + sc];
            a01 = *(const float4*)&A[(size_t)(m0 + sr) * lda + k0 + sc + 16];
            a10 = *(const float4*)&A[(size_t)(m0 + sr + 64) * lda + k0 + sc];
            a11 = *(const float4*)&A[(size_t)(m0 + sr + 64) * lda + k0 + sc + 16];
            b00 = make_float4(0.f,0.f,0.f,0.f); b01 = b00; b10 = b00; b11 = b00;
            if (n0 + sr < N) {
                b00 = *(const float4*)&W[(size_t)(n0 + sr) * K + k0 + sc];
                b01 = *(const float4*)&W[(size_t)(n0 + sr) * K + k0 + sc + 16];
            }
            if (n0 + sr + 64 < N) {
                b10 = *(const float4*)&W[(size_t)(n0 + sr + 64) * K + k0 + sc];
                b11 = *(const float4*)&W[(size_t)(n0 + sr + 64) * K + k0 + sc + 16];
            }
        }

        const uint32_t bAH = base + (cur * BUF_W) * 4;
        const uint32_t bAL = bAH + TILE_W * 4;
        const uint32_t bBH = bAH + 2 * TILE_W * 4;
        const uint32_t bBL = bAH + 3 * TILE_W * 4;
#pragma unroll
        for (int kk = 0; kk < 2; ++kk) {
            uint32_t ah[4][4], al[4][4];
#pragma unroll
            for (int mt = 0; mt < 4; ++mt) {
                const uint32_t off = (((wm * 64 + mt * 16 + rA) * 20) + kk * 8 + cA) * 4;
                ldsm_x4(ah[mt], bAH + off);
                ldsm_x4(al[mt], bAL + off);
            }
            uint32_t bh[2][4], bl[2][4];
#pragma unroll
            for (int np = 0; np < 2; ++np) {
                const uint32_t off = (((wn * 32 + np * 16 + rB) * 20) + kk * 8 + cB) * 4;
                ldsm_x4(bh[np], bBH + off);
                ldsm_x4(bl[np], bBL + off);
            }
#pragma unroll
            for (int mt = 0; mt < 4; ++mt)
#pragma unroll
                for (int nt = 0; nt < 4; ++nt) {
                    const int np = nt >> 1, e0 = (nt & 1) * 2, e1 = e0 + 1;
                    mma_bf16(acc[mt][nt], ah[mt], bl[np][e0], bl[np][e1]);
                    mma_bf16(acc[mt][nt], al[mt], bh[np][e0], bh[np][e1]);
                    mma_bf16(acc[mt][nt], ah[mt], bh[np][e0], bh[np][e1]);
                }
        }

        if (more) {
            const int nxt = cur ^ 1;
            uint32_t* AH = sm + nxt * BUF_W; uint32_t* AL = AH + TILE_W;
            uint32_t* BH = AH + 2 * TILE_W;  uint32_t* BL = AH + 3 * TILE_W;
            split_store_bf(&AH[sr*20 + wc],          &AL[sr*20 + wc],          a00);
            split_store_bf(&AH[sr*20 + wc + 8],      &AL[sr*20 + wc + 8],      a01);
            split_store_bf(&AH[(sr+64)*20 + wc],     &AL[(sr+64)*20 + wc],     a10);
            split_store_bf(&AH[(sr+64)*20 + wc + 8], &AL[(sr+64)*20 + wc + 8], a11);
            split_store_bf(&BH[sr*20 + wc],          &BL[sr*20 + wc],          b00);
            split_store_bf(&BH[sr*20 + wc + 8],      &BL[sr*20 + wc + 8],      b01);
            split_store_bf(&BH[(sr+64)*20 + wc],     &BL[(sr+64)*20 + wc],     b10);
            split_store_bf(&BH[(sr+64)*20 + wc + 8], &BL[(sr+64)*20 + wc + 8], b11);
        }
        __syncthreads();
    }

    const int er = lane >> 2;
    const int ec = (lane & 3) * 2;
#pragma unroll
    for (int mt = 0; mt < 4; ++mt) {
        const int r0 = m0 + wm * 64 + mt * 16 + er;
#pragma unroll
        for (int nt = 0; nt < 4; ++nt) {
            const int cc = n0 + wn * 32 + nt * 8 + ec;
            if (cc >= N) continue;
            float v0 = acc[mt][nt][0], v1 = acc[mt][nt][1];
            float v2 = acc[mt][nt][2], v3 = acc[mt][nt][3];
            if (EP == 4) {
                const float bb0 = bias[cc], bb1 = bias[cc + 1];
                float vv[4] = {v0 + bb0, v1 + bb1, v2 + bb0, v3 + bb1};
                float dt[4], pp[4];
#pragma unroll
                for (int i = 0; i < 4; i++) {
                    float v = vv[i];
                    float e = __expf(-fabsf(v));
                    dt[i] = fmaxf(v, 0.f) + __logf(1.f + e);
                    pp[i] = __fdividef((v > 0.f ? e : 1.f), 1.f + e);
                }
                float4 o;
                o.x = dt[0]; o.y = pp[0]; o.z = dt[1]; o.w = pp[1];
                *(float4*)&C[2 * ((size_t)r0 * ldc + cc)] = o;
                o.x = dt[2]; o.y = pp[2]; o.z = dt[3]; o.w = pp[3];
                *(float4*)&C[2 * ((size_t)(r0 + 8) * ldc + cc)] = o;
            } else {
                if (EP == 3) {
                    const float bb0 = bias[cc], bb1 = bias[cc + 1];
                    v0 += bb0; v1 += bb1; v2 += bb0; v3 += bb1;
                }
                const size_t o0 = (size_t)r0 * ldc + cc;
                const size_t o1 = (size_t)(r0 + 8) * ldc + cc;
                float2 s;
                s.x = v0; s.y = v1; *(float2*)&C[o0] = s;
                s.x = v2; s.y = v3; *(float2*)&C[o1] = s;
            }
        }
    }
}

// ---------------- transposes -------------------------------------------------
__global__ void transpose_in_k(const float* __restrict__ in, float* __restrict__ inT)
{
    __shared__ float tile[32][33];
    int b  = blockIdx.z;
    int n0 = blockIdx.y * 32;
    int l0 = blockIdx.x * 32;
    int tx = threadIdx.x, ty = threadIdx.y;
    for (int i = ty; i < 32; i += 8)
        tile[i][tx] = in[(size_t)b * NUML * SEQ + (size_t)(n0 + i) * SEQ + l0 + tx];
    __syncthreads();
    for (int i = ty; i < 32; i += 8)
        inT[(size_t)(b * SEQ + l0 + i) * NUML + n0 + tx] = tile[tx][i];
}
__global__ void transpose_out_k(const float* __restrict__ Ct, float* __restrict__ out)
{
    __shared__ float tile[32][33];
    int b  = blockIdx.z;
    int l0 = blockIdx.x * 32;
    int p0 = blockIdx.y * 32;
    int tx = threadIdx.x, ty = threadIdx.y;
    for (int i = ty; i < 32; i += 8)
        tile[i][tx] = Ct[(size_t)(b * SEQ + l0 + i) * PREDL + p0 + tx];
    __syncthreads();
    for (int i = ty; i < 32; i += 8)
        out[(size_t)b * PREDL * SEQ + (size_t)(p0 + i) * SEQ + l0 + tx] = tile[tx][i];
}

// ---------------- depthwise conv + silu, 4 t-rows per thread ------------------
__global__ void conv_silu_k(const float* __restrict__ xz, const float* __restrict__ cw,
                            const float* __restrict__ cb, float* __restrict__ xc, int rev)
{
    const int i = blockIdx.x * blockDim.x + threadIdx.x;
    const int d4 = (i & 255) * 4;
    const int g  = i >> 8;
    const int t0 = (g & 255) * 4;
    const int b  = g >> 8;

    float4 w[4];
    w[0] = *(const float4*)&cw[(d4 + 0) * 4];
    w[1] = *(const float4*)&cw[(d4 + 1) * 4];
    w[2] = *(const float4*)&cw[(d4 + 2) * 4];
    w[3] = *(const float4*)&cw[(d4 + 3) * 4];
    const float4 bias = *(const float4*)&cb[d4];
    float4 out[4] = {bias, bias, bias, bias};

    const int jlo = rev ? 0 : -3;
#pragma unroll
    for (int jj = 0; jj < 7; jj++) {
        const int tt = t0 + jlo + jj;
        if ((unsigned)tt >= SEQ) continue;
        const float4 v = *(const float4*)&xz[(size_t)(b * SEQ + tt) * (2 * DINNER) + d4];
#pragma unroll
        for (int o = 0; o < 4; o++) {
            const int m = jj - o;
            if (m < 0 || m > 3) continue;
            const int k = rev ? (3 - m) : m;
            out[o].x = fmaf((&w[0].x)[k], v.x, out[o].x);
            out[o].y = fmaf((&w[1].x)[k], v.y, out[o].y);
            out[o].z = fmaf((&w[2].x)[k], v.z, out[o].z);
            out[o].w = fmaf((&w[3].x)[k], v.w, out[o].w);
        }
    }
#pragma unroll
    for (int o = 0; o < 4; o++) {
        float4 r = out[o];
        r.x = silu_f(r.x); r.y = silu_f(r.y);
        r.z = silu_f(r.z); r.w = silu_f(r.w);
        *(float4*)&xc[(size_t)(b * SEQ + t0 + o) * DINNER + d4] = r;
    }
}

// ---------------- selective scan, 4 lanes per (b,d), 4-deep prefetch ----------
__global__ void scan_k(const float2* __restrict__ dtp, const float* __restrict__ xcp,
                       const float* __restrict__ xdbl, const float* __restrict__ xz,
                       const float* __restrict__ a_log, const float* __restrict__ d_skip,
                       __nv_bfloat16* __restrict__ ysh, __nv_bfloat16* __restrict__ ysl,
                       int rev)
{
    int idx = blockIdx.x * blockDim.x + threadIdx.x;
    int q   = idx & 3;
    int gid = idx >> 2;
    int d = gid & (DINNER - 1);
    int b = gid >> 10;

    float A0 = -__expf(a_log[d * DSTATE + 4 * q + 0]);
    float A1 = -__expf(a_log[d * DSTATE + 4 * q + 1]);
    float A2 = -__expf(a_log[d * DSTATE + 4 * q + 2]);
    float A3 = -__expf(a_log[d * DSTATE + 4 * q + 3]);
    bool fast = fabsf(A0 + (4 * q + 1)) < 1e-4f && fabsf(A1 + (4 * q + 2)) < 1e-4f &&
                fabsf(A2 + (4 * q + 3)) < 1e-4f && fabsf(A3 + (4 * q + 4)) < 1e-4f;
    fast = __all_sync(0xffffffffu, fast);

    float h0 = 0.f, h1 = 0.f, h2 = 0.f, h3 = 0.f;
    const float Dp = d_skip[d];

    float2 dpb[4]; float xb[4]; float4 Bb[4], Cb[4]; float zb[4];
#pragma unroll
    for (int j = 0; j < 4; j++) {
        const int tt = rev ? (SEQ - 1 - j) : j;
        const size_t r = (size_t)b * SEQ + tt;
        dpb[j] = dtp[r * DINNER + d];
        xb[j]  = xcp[r * DINNER + d];
        Bb[j]  = *(const float4*)&xdbl[r * 64 + 32 + 4 * q];
        Cb[j]  = *(const float4*)&xdbl[r * 64 + 48 + 4 * q];
        zb[j]  = xz[r * (2 * DINNER) + DINNER + d];
    }

#pragma unroll 4
    for (int step = 0; step < SEQ; ++step) {
        const int j = step & 3;
        const int tc = rev ? (SEQ - 1 - step) : step;
        const size_t rc = (size_t)b * SEQ + tc;
        const float2 dpc = dpb[j];
        const float  xc_ = xb[j];
        const float4 Bc = Bb[j], Cc = Cb[j];
        const float  zc = zb[j];

        if (step + 4 < SEQ) {
            const int tn = rev ? (SEQ - 5 - step) : (step + 4);
            const size_t rn = (size_t)b * SEQ + tn;
            dpb[j] = dtp[rn * DINNER + d];
            xb[j]  = xcp[rn * DINNER + d];
            Bb[j]  = *(const float4*)&xdbl[rn * 64 + 32 + 4 * q];
            Cb[j]  = *(const float4*)&xdbl[rn * 64 + 48 + 4 * q];
            zb[j]  = xz[rn * (2 * DINNER) + DINNER + d];
        }

        const float dtx = dpc.x * xc_;
        float dA0, dA1, dA2, dA3;
        if (fast) {
            const float p  = dpc.y;
            const float p2 = p * p, p4 = p2 * p2, p8 = p4 * p4;
            float m = 1.f;
            if (q & 1) m = p4;
            if (q & 2) m *= p8;
            dA0 = m * p; dA1 = dA0 * p; dA2 = dA1 * p; dA3 = dA2 * p;
        } else {
            dA0 = __expf(dpc.x * A0); dA1 = __expf(dpc.x * A1);
            dA2 = __expf(dpc.x * A2); dA3 = __expf(dpc.x * A3);
        }
        h0 = fmaf(dA0, h0, dtx * Bc.x);
        h1 = fmaf(dA1, h1, dtx * Bc.y);
        h2 = fmaf(dA2, h2, dtx * Bc.z);
        h3 = fmaf(dA3, h3, dtx * Bc.w);
        float yp = (h0 * Cc.x + h1 * Cc.y) + (h2 * Cc.z + h3 * Cc.w);
        yp += __shfl_xor_sync(0xffffffffu, yp, 1);
        yp += __shfl_xor_sync(0xffffffffu, yp, 2);
        if (q == 0) {
            const float yv = (yp + xc_ * Dp) * silu_f(zc);
            const __nv_bfloat16 hb = __float2bfloat16_rn(yv);
            ysh[rc * DINNER + d] = hb;
            ysl[rc * DINNER + d] = __float2bfloat16_rn(yv - __bfloat162float(hb));
        }
    }
}

// ---------------- silu(a + a2) + dual-bf16 plane emit --------------------------
// WRITE_F32: fp32 output store is elided when no later consumer exists (layer 0).
template<int WRITE_F32>
__global__ void silu3_k(const float4* __restrict__ a, const float4* __restrict__ a2,
                        float4* __restrict__ o,
                        __nv_bfloat16* __restrict__ h, __nv_bfloat16* __restrict__ l, int n4)
{
    int i = blockIdx.x * blockDim.x + threadIdx.x;
    if (i >= n4) return;
    float4 v = a[i];
    const float4 w = a2[i];
    v.x = silu_f(v.x + w.x); v.y = silu_f(v.y + w.y);
    v.z = silu_f(v.z + w.z); v.w = silu_f(v.w + w.w);
    if (WRITE_F32) o[i] = v;
    __nv_bfloat162 h0 = __floats2bfloat162_rn(v.x, v.y);
    __nv_bfloat162 h1 = __floats2bfloat162_rn(v.z, v.w);
    __nv_bfloat162 l0 = __floats2bfloat162_rn(v.x - __bfloat162float(h0.x),
                                              v.y - __bfloat162float(h0.y));
    __nv_bfloat162 l1 = __floats2bfloat162_rn(v.z - __bfloat162float(h1.x),
                                              v.w - __bfloat162float(h1.y));
    ((__nv_bfloat162*)h)[i * 2]     = h0;
    ((__nv_bfloat162*)h)[i * 2 + 1] = h1;
    ((__nv_bfloat162*)l)[i * 2]     = l0;
    ((__nv_bfloat162*)l)[i * 2 + 1] = l1;
}

// ---------------- fp32 -> bf16 hi/lo split ------------------------------------
__global__ void split_k(const float* __restrict__ a, __nv_bfloat16* __restrict__ h,
                        __nv_bfloat16* __restrict__ l, int n)
{
    int i = blockIdx.x * blockDim.x + threadIdx.x;
    if (i >= n) return;
    const float v = a[i];
    const __nv_bfloat16 hb = __float2bfloat16_rn(v);
    h[i] = hb;
    l[i] = __float2bfloat16_rn(v - __bfloat162float(hb));
}

// ---------------- launcher ---------------------------------------------------
extern "C" void kernel_launch(void* const* d_in, const int* in_sizes, int n_in,
                              void* d_out, int out_size)
{
    (void)in_sizes; (void)n_in; (void)out_size;
    const float* inputs = (const float*)d_in[0];
    const float* w1     = (const float*)d_in[1];
    const float* b1     = (const float*)d_in[2];
    const float* w_in   = (const float*)d_in[3];
    const float* conv_w = (const float*)d_in[4];
    const float* conv_b = (const float*)d_in[5];
    const float* w_xp   = (const float*)d_in[6];
    const float* w_dt   = (const float*)d_in[7];
    const float* b_dt   = (const float*)d_in[8];
    const float* a_log  = (const float*)d_in[9];
    const float* d_skip = (const float*)d_in[10];
    const float* w_out  = (const float*)d_in[11];
    const float* w2     = (const float*)d_in[12];
    const float* b2     = (const float*)d_in[13];

    float *inT, *emb, *acc, *acc2, *xzA, *xzB, *xcA, *xcB, *xdA, *xdB, *dtA, *dtB;
    __nv_bfloat16 *embh, *embl, *yshA, *yslA, *yshB, *yslB, *winh, *winl, *wouth, *woutl;
    cudaGetSymbolAddress((void**)&inT,   g_inT);
    cudaGetSymbolAddress((void**)&emb,   g_emb);
    cudaGetSymbolAddress((void**)&acc,   g_acc);
    cudaGetSymbolAddress((void**)&acc2,  g_acc2);
    cudaGetSymbolAddress((void**)&xzA,   g_xz);
    cudaGetSymbolAddress((void**)&xzB,   g_xz2);
    cudaGetSymbolAddress((void**)&xcA,   g_xc);
    cudaGetSymbolAddress((void**)&xcB,   g_xc2);
    cudaGetSymbolAddress((void**)&xdA,   g_xdbl);
    cudaGetSymbolAddress((void**)&xdB,   g_xdbl2);
    cudaGetSymbolAddress((void**)&dtA,   g_dtp);
    cudaGetSymbolAddress((void**)&dtB,   g_dtp2);
    cudaGetSymbolAddress((void**)&embh,  g_embh);
    cudaGetSymbolAddress((void**)&embl,  g_embl);
    cudaGetSymbolAddress((void**)&yshA,  g_ysh);
    cudaGetSymbolAddress((void**)&yslA,  g_ysl);
    cudaGetSymbolAddress((void**)&yshB,  g_ysh2);
    cudaGetSymbolAddress((void**)&yslB,  g_ysl2);
    cudaGetSymbolAddress((void**)&winh,  g_winh);
    cudaGetSymbolAddress((void**)&winl,  g_winl);
    cudaGetSymbolAddress((void**)&wouth, g_wouth);
    cudaGetSymbolAddress((void**)&woutl, g_woutl);

    cudaFuncSetAttribute(gemm_tc<0>, cudaFuncAttributeMaxDynamicSharedMemorySize, SMEM_BYT);
    cudaFuncSetAttribute(gemm_tc<3>, cudaFuncAttributeMaxDynamicSharedMemorySize, SMEM_BYT);
    cudaFuncSetAttribute(gemm_tc<4>, cudaFuncAttributeMaxDynamicSharedMemorySize, SMEM_BYT);
    cudaFuncSetAttribute(gemm_bf<0>, cudaFuncAttributeMaxDynamicSharedMemorySize, BF_SMEM);

    // secondary stream + events (created once; no device memory)
    static cudaStream_t s2 = 0;
    static cudaEvent_t evF[2], evJ[2], evS, evW;
    if (!s2) {
        cudaStreamCreateWithFlags(&s2, cudaStreamNonBlocking);
        for (int i = 0; i < 2; i++) {
            cudaEventCreateWithFlags(&evF[i], cudaEventDisableTiming);
            cudaEventCreateWithFlags(&evJ[i], cudaEventDisableTiming);
        }
        cudaEventCreateWithFlags(&evS, cudaEventDisableTiming);
        cudaEventCreateWithFlags(&evW, cudaEventDisableTiming);
    }

    dim3 tb(32, 8);

    // fork: weight splits run on s2, overlapped with the embedding chain
    cudaEventRecord(evS, 0);
    cudaStreamWaitEvent(s2, evS, 0);
    split_k<<<(4*2*DINNER*DMODEL + 255)/256, 256, 0, s2>>>(
        w_in,  winh,  winl,  4*2*DINNER*DMODEL);
    split_k<<<(4*DMODEL*DINNER  + 255)/256, 256, 0, s2>>>(
        w_out, wouth, woutl, 4*DMODEL*DINNER);
    cudaEventRecord(evW, s2);

    transpose_in_k<<<dim3(SEQ / 32, NUML / 32, BATCH), tb>>>(inputs, inT);
    gemm_tc<3><<<dim3(DMODEL / 128, MROWS / 128), 256, SMEM_BYT>>>(
        inT, NUML, w1, b1, emb, DMODEL, DMODEL, NUML);
    split_k<<<(MROWS*DMODEL + 255)/256, 256>>>(emb, embh, embl, MROWS*DMODEL);

    // join: layer loop needs the split weights on both streams
    cudaStreamWaitEvent(0, evW, 0);

    for (int layer = 0; layer < 2; ++layer) {
        cudaEventRecord(evF[layer], 0);
        cudaStreamWaitEvent(s2, evF[layer], 0);

        for (int dir = 0; dir < 2; ++dir) {
            const int off = dir * 2 + layer;
            cudaStream_t st = dir ? s2 : 0;
            float* xz  = dir ? xzB : xzA;
            float* xc  = dir ? xcB : xcA;
            float* xd  = dir ? xdB : xdA;
            float* dtp = dir ? dtB : dtA;
            __nv_bfloat16* ysh = dir ? yshB : yshA;
            __nv_bfloat16* ysl = dir ? yslB : yslA;
            float* accD = dir ? acc2 : acc;

            const __nv_bfloat16* Winh = winh + (size_t)off * 2 * DINNER * DMODEL;
            const __nv_bfloat16* Winl = winl + (size_t)off * 2 * DINNER * DMODEL;
            const __nv_bfloat16* Wouh = wouth + (size_t)off * DMODEL * DINNER;
            const __nv_bfloat16* Woul = woutl + (size_t)off * DMODEL * DINNER;
            const float* cw   = conv_w + (size_t)off * DINNER * 4;
            const float* cb   = conv_b + (size_t)off * DINNER;
            const float* Wxp  = w_xp   + (size_t)off * 64 * DINNER;
            const float* Wdt  = w_dt   + (size_t)off * DINNER * DTRANK;
            const float* bdt  = b_dt   + (size_t)off * DINNER;
            const float* Al   = a_log  + (size_t)off * DINNER * DSTATE;
            const float* Dp   = d_skip + (size_t)off * DINNER;

            gemm_bf<0><<<dim3(2 * DINNER / 128, MROWS / 128), 256, BF_SMEM, st>>>(
                embh, embl, Winh, Winl, xz, 2 * DINNER, DMODEL);

            conv_silu_k<<<(MROWS / 4) * (DINNER / 4) / 256, 256, 0, st>>>(xz, cw, cb, xc, dir);

            gemm_tc<0><<<dim3(1, MROWS / 128), 256, SMEM_BYT, st>>>(
                xc, DINNER, Wxp, nullptr, xd, 64, 64, DINNER);

            gemm_tc<4><<<dim3(DINNER / 128, MROWS / 128), 256, SMEM_BYT, st>>>(
                xd, 64, Wdt, bdt, dtp, DINNER, DINNER, DTRANK);

            scan_k<<<(BATCH * DINNER * 4) / 256, 256, 0, st>>>(
                (const float2*)dtp, xc, xd, xz, Al, Dp, ysh, ysl, dir);

            gemm_bf<0><<<dim3(DMODEL / 128, MROWS / 128), 256, BF_SMEM, st>>>(
                ysh, ysl, Wouh, Woul, accD, DMODEL, DINNER);
        }

        cudaEventRecord(evJ[layer], s2);
        cudaStreamWaitEvent(0, evJ[layer], 0);

        if (layer == 0)
            silu3_k<0><<<(MROWS * DMODEL / 4 + 255) / 256, 256>>>(
                (const float4*)acc, (const float4*)acc2, (float4*)emb, embh, embl,
                MROWS * DMODEL / 4);
        else
            silu3_k<1><<<(MROWS * DMODEL / 4 + 255) / 256, 256>>>(
                (const float4*)acc, (const float4*)acc2, (float4*)emb, embh, embl,
                MROWS * DMODEL / 4);
    }

    gemm_tc<3><<<dim3(2, MROWS / 128), 256, SMEM_BYT>>>(
        emb, DMODEL, w2, b2, acc, PREDL, PREDL, DMODEL);

    transpose_out_k<<<dim3(SEQ / 32, PREDL / 32, BATCH), tb>>>(acc, (float*)d_out);
}

// round 16
// speedup vs baseline: 1.0214x; 1.0080x over previous
#include <cuda_runtime.h>
#include <cuda_bf16.h>
#include <math.h>
#include <stdint.h>

#define BATCH  16
#define SEQ    1024
#define DMODEL 512
#define DINNER 1024
#define DTRANK 32
#define DSTATE 16
#define PREDL  192
#define PREDP  256              // padded PREDL for tile-aligned final GEMM
#define NUML   96
#define MROWS  (BATCH*SEQ)      // 16384

// ---------------- scratch (device globals; no allocations allowed) ----------
__device__ float g_inT [MROWS*NUML];
__device__ float g_acc [MROWS*DMODEL];
__device__ float g_acc2[MROWS*DMODEL];
__device__ float g_xz  [MROWS*2*DINNER];
__device__ float g_xz2 [MROWS*2*DINNER];
__device__ float g_xc  [MROWS*DINNER];
__device__ float g_xc2 [MROWS*DINNER];
__device__ float g_xdbl [MROWS*64];
__device__ float g_xdbl2[MROWS*64];
__device__ float g_dtp [MROWS*DINNER*2];   // interleaved (dt, exp(-dt))
__device__ float g_dtp2[MROWS*DINNER*2];
__device__ float g_fin [MROWS*PREDP];      // final projection output (ld=256)
__device__ __nv_bfloat16 g_embh[MROWS*DMODEL];
__device__ __nv_bfloat16 g_embl[MROWS*DMODEL];
__device__ __nv_bfloat16 g_ysh [MROWS*DINNER];
__device__ __nv_bfloat16 g_ysl [MROWS*DINNER];
__device__ __nv_bfloat16 g_ysh2[MROWS*DINNER];
__device__ __nv_bfloat16 g_ysl2[MROWS*DINNER];
__device__ __nv_bfloat16 g_winh[4*2*DINNER*DMODEL];
__device__ __nv_bfloat16 g_winl[4*2*DINNER*DMODEL];
__device__ __nv_bfloat16 g_wouth[4*DMODEL*DINNER];
__device__ __nv_bfloat16 g_woutl[4*DMODEL*DINNER];
__device__ __nv_bfloat16 g_w2h [PREDP*DMODEL];
__device__ __nv_bfloat16 g_w2l [PREDP*DMODEL];
__device__ float g_b2p [PREDP];

__device__ __forceinline__ float silu_f(float x) {
    return x * (1.f / (1.f + __expf(-x)));
}

__device__ __forceinline__ void ldsm_x4(uint32_t (&r)[4], uint32_t addr) {
    asm volatile("ldmatrix.sync.aligned.m8n8.x4.shared.b16 {%0,%1,%2,%3}, [%4];"
                 : "=r"(r[0]), "=r"(r[1]), "=r"(r[2]), "=r"(r[3]) : "r"(addr));
}
__device__ __forceinline__ void mma_bf16(float (&c)[4], const uint32_t (&a)[4],
                                         uint32_t b0, uint32_t b1) {
    asm volatile("mma.sync.aligned.m16n8k16.row.col.f32.bf16.bf16.f32 "
                 "{%0,%1,%2,%3}, {%4,%5,%6,%7}, {%8,%9}, {%0,%1,%2,%3};"
                 : "+f"(c[0]), "+f"(c[1]), "+f"(c[2]), "+f"(c[3])
                 : "r"(a[0]), "r"(a[1]), "r"(a[2]), "r"(a[3]), "r"(b0), "r"(b1));
}
__device__ __forceinline__ void cpa16(uint32_t saddr, const void* g) {
    asm volatile("cp.async.cg.shared.global [%0], [%1], 16;"
                 :: "r"(saddr), "l"(g) : "memory");
}
#define CPA_COMMIT() asm volatile("cp.async.commit_group;" ::: "memory")
#define CPA_WAIT(n)  asm volatile("cp.async.wait_group %0;" :: "n"(n) : "memory")

// ============ pipelined bf16-plane GEMM:  C[M,N] = A @ W^T ===================
// 128x128 tile, BK=32, 3-stage cp.async, XOR-swizzled 16-word rows, 2 CTA/SM.
// EP: 0 = write, 3 = +bias then write.
#define BF_TILE_W  (128*16)
#define BF_STAGE_W (4*BF_TILE_W)
#define BF_SMEM    (3*BF_STAGE_W*4)  // 98304 B

template<int EP>
__global__ __launch_bounds__(256, 2) void gemm_bf(
    const __nv_bfloat16* __restrict__ Ah, const __nv_bfloat16* __restrict__ Al,
    const __nv_bfloat16* __restrict__ Wh, const __nv_bfloat16* __restrict__ Wl,
    const float* __restrict__ bias,
    float* __restrict__ C, int ldc, int K)
{
    extern __shared__ uint32_t sm[];
    const int t = threadIdx.x, lane = t & 31, warp = t >> 5;
    const int wm = warp >> 2, wn = warp & 3;
    const int m0 = blockIdx.y * 128, n0 = blockIdx.x * 128;
    const int nIt = K >> 5;
    const uint32_t base = (uint32_t)__cvta_generic_to_shared(&sm[0]);

    const int rA = ((lane >> 3) & 1) * 8 + (lane & 7);
    const int chA0 = (lane >> 4);
    const int rB = ((lane >> 4) & 1) * 8 + (lane & 7);
    const int chB0 = ((lane >> 3) & 1);

    float acc[4][4][4];
#pragma unroll
    for (int i = 0; i < 4; i++)
#pragma unroll
        for (int j = 0; j < 4; j++)
#pragma unroll
            for (int k = 0; k < 4; k++) acc[i][j][k] = 0.f;

    auto load_stage = [&](int s, int kb) {
        const uint32_t st = base + s * BF_STAGE_W * 4;
        const int koff = kb * 32;
#pragma unroll
        for (int i = 0; i < 8; i++) {
            const int c = t + i * 256;
            const int tile = c >> 9;
            const int w = c & 511;
            const int row = w >> 2;
            const int ch  = w & 3;
            const int chs = ch ^ ((row >> 1) & 3);
            const uint32_t sa = st + (tile * BF_TILE_W + row * 16 + chs * 4) * 4;
            const __nv_bfloat16* P = (tile == 0) ? Ah : (tile == 1) ? Al
                                   : (tile == 2) ? Wh : Wl;
            const int grow = ((tile < 2) ? m0 : n0) + row;
            cpa16(sa, P + (size_t)grow * K + koff + ch * 8);
        }
        CPA_COMMIT();
    };

    load_stage(0, 0);
    if (nIt > 1) load_stage(1, 1);

    for (int it = 0; it < nIt; ++it) {
        if (it + 2 < nIt) load_stage((it + 2) % 3, it + 2);
        if (it + 2 < nIt)      { CPA_WAIT(2); }
        else if (it + 1 < nIt) { CPA_WAIT(1); }
        else                   { CPA_WAIT(0); }
        __syncthreads();

        const uint32_t bAH = base + ((it % 3) * BF_STAGE_W) * 4;
        const uint32_t bAL = bAH + BF_TILE_W * 4;
        const uint32_t bBH = bAH + 2 * BF_TILE_W * 4;
        const uint32_t bBL = bAH + 3 * BF_TILE_W * 4;
#pragma unroll
        for (int kk = 0; kk < 2; ++kk) {
            uint32_t bh[2][4], bl[2][4];
            const int chB = kk * 2 + chB0;
#pragma unroll
            for (int np = 0; np < 2; ++np) {
                const int rowB = wn * 32 + np * 16 + rB;
                const uint32_t off = (rowB * 16 + ((chB ^ ((rowB >> 1) & 3)) * 4)) * 4;
                ldsm_x4(bh[np], bBH + off);
                ldsm_x4(bl[np], bBL + off);
            }
            const int chA = kk * 2 + chA0;
#pragma unroll
            for (int mt = 0; mt < 4; ++mt) {
                const int rowA = wm * 64 + mt * 16 + rA;
                const uint32_t off = (rowA * 16 + ((chA ^ ((rowA >> 1) & 3)) * 4)) * 4;
                uint32_t ah[4];
                ldsm_x4(ah, bAH + off);
#pragma unroll
                for (int nt = 0; nt < 4; ++nt) {
                    const int np = nt >> 1, e0 = (nt & 1) * 2, e1 = e0 + 1;
                    mma_bf16(acc[mt][nt], ah, bh[np][e0], bh[np][e1]);
                    mma_bf16(acc[mt][nt], ah, bl[np][e0], bl[np][e1]);
                }
                uint32_t al[4];
                ldsm_x4(al, bAL + off);
#pragma unroll
                for (int nt = 0; nt < 4; ++nt) {
                    const int np = nt >> 1, e0 = (nt & 1) * 2, e1 = e0 + 1;
                    mma_bf16(acc[mt][nt], al, bh[np][e0], bh[np][e1]);
                }
            }
        }
        __syncthreads();
    }

    const int er = lane >> 2;
    const int ec = (lane & 3) * 2;
#pragma unroll
    for (int mt = 0; mt < 4; ++mt) {
        const int r0 = m0 + wm * 64 + mt * 16 + er;
#pragma unroll
        for (int nt = 0; nt < 4; ++nt) {
            const int cc = n0 + wn * 32 + nt * 8 + ec;
            float v0 = acc[mt][nt][0], v1 = acc[mt][nt][1];
            float v2 = acc[mt][nt][2], v3 = acc[mt][nt][3];
            if (EP == 3) {
                const float bb0 = bias[cc], bb1 = bias[cc + 1];
                v0 += bb0; v1 += bb1; v2 += bb0; v3 += bb1;
            }
            const size_t o0 = (size_t)r0 * ldc + cc;
            const size_t o1 = (size_t)(r0 + 8) * ldc + cc;
            float2 s;
            s.x = v0; s.y = v1; *(float2*)&C[o0] = s;
            s.x = v2; s.y = v3; *(float2*)&C[o1] = s;
        }
    }
}

// ====================== fp32-input mma.sync GEMM (small shapes) ==============
__device__ __forceinline__ void split_store_bf(uint32_t* hiP, uint32_t* loP, float4 v) {
    __nv_bfloat162 h0 = __floats2bfloat162_rn(v.x, v.y);
    __nv_bfloat162 h1 = __floats2bfloat162_rn(v.z, v.w);
    float lx = v.x - __bfloat162float(h0.x);
    float ly = v.y - __bfloat162float(h0.y);
    float lz = v.z - __bfloat162float(h1.x);
    float lw = v.w - __bfloat162float(h1.y);
    __nv_bfloat162 l0 = __floats2bfloat162_rn(lx, ly);
    __nv_bfloat162 l1 = __floats2bfloat162_rn(lz, lw);
    uint2 hu, lu;
    hu.x = *(uint32_t*)&h0; hu.y = *(uint32_t*)&h1;
    lu.x = *(uint32_t*)&l0; lu.y = *(uint32_t*)&l1;
    *(uint2*)hiP = hu;
    *(uint2*)loP = lu;
}

#define TILE_W   (128*20)
#define BUF_W    (4*TILE_W)
#define SMEM_BYT (2*BUF_W*4)   // 81920

// EP: 0 = none, 4 = +bias softplus (dt, exp(-dt)), 5 = +bias, split to bf16 planes
template<int EP>
__global__ __launch_bounds__(256) void gemm_tc(
    const float* __restrict__ A, int lda,
    const float* __restrict__ W,
    const float* __restrict__ bias,
    float* __restrict__ C, int ldc,
    int N, int K,
    __nv_bfloat16* __restrict__ Oh, __nv_bfloat16* __restrict__ Ol)
{
    extern __shared__ uint32_t sm[];

    const int t    = threadIdx.x;
    const int lane = t & 31, warp = t >> 5;
    const int wm   = warp >> 2, wn = warp & 3;
    const int m0   = blockIdx.y * 128, n0 = blockIdx.x * 128;

    const int sr = t >> 2;
    const int sc = (t & 3) * 4;

    const int rA = ((lane >> 3) & 1) * 8 + (lane & 7);
    const int cA = (lane >> 4) * 4;
    const int rB = ((lane >> 4) & 1) * 8 + (lane & 7);
    const int cB = ((lane >> 3) & 1) * 4;

    float acc[4][4][4];
#pragma unroll
    for (int i = 0; i < 4; i++)
#pragma unroll
        for (int j = 0; j < 4; j++)
#pragma unroll
            for (int k = 0; k < 4; k++) acc[i][j][k] = 0.f;

    const int nIt = K >> 5;
    const uint32_t base = (uint32_t)__cvta_generic_to_shared(&sm[0]);
    const int wc = sc >> 1;

    float4 a00, a01, a10, a11, b00, b01, b10, b11;
    {
        a00 = *(const float4*)&A[(size_t)(m0 + sr) * lda + sc];
        a01 = *(const float4*)&A[(size_t)(m0 + sr) * lda + sc + 16];
        a10 = *(const float4*)&A[(size_t)(m0 + sr + 64) * lda + sc];
        a11 = *(const float4*)&A[(size_t)(m0 + sr + 64) * lda + sc + 16];
        b00 = make_float4(0.f,0.f,0.f,0.f); b01 = b00; b10 = b00; b11 = b00;
        if (n0 + sr < N) {
            b00 = *(const float4*)&W[(size_t)(n0 + sr) * K + sc];
            b01 = *(const float4*)&W[(size_t)(n0 + sr) * K + sc + 16];
        }
        if (n0 + sr + 64 < N) {
            b10 = *(const float4*)&W[(size_t)(n0 + sr + 64) * K + sc];
            b11 = *(const float4*)&W[(size_t)(n0 + sr + 64) * K + sc + 16];
        }
        uint32_t* AH = sm;              uint32_t* AL = sm + TILE_W;
        uint32_t* BH = sm + 2 * TILE_W; uint32_t* BL = sm + 3 * TILE_W;
        split_store_bf(&AH[sr*20 + wc],            &AL[sr*20 + wc],            a00);
        split_store_bf(&AH[sr*20 + wc + 8],        &AL[sr*20 + wc + 8],        a01);
        split_store_bf(&AH[(sr+64)*20 + wc],       &AL[(sr+64)*20 + wc],       a10);
        split_store_bf(&AH[(sr+64)*20 + wc + 8],   &AL[(sr+64)*20 + wc + 8],   a11);
        split_store_bf(&BH[sr*20 + wc],            &BL[sr*20 + wc],            b00);
        split_store_bf(&BH[sr*20 + wc + 8],        &BL[sr*20 + wc + 8],        b01);
        split_store_bf(&BH[(sr+64)*20 + wc],       &BL[(sr+64)*20 + wc],       b10);
        split_store_bf(&BH[(sr+64)*20 + wc + 8],   &BL[(sr+64)*20 + wc + 8],   b11);
    }
    __syncthreads();

    for (int it = 0; it < nIt; ++it) {
        const int cur = it & 1;
        const bool more = (it + 1 < nIt);
        if (more) {
            int k0 = (it + 1) << 5;
            a00 = *(const float4*)&A[(size_t)(m0 + sr) * lda + k0 + sc];
            a01 = *(const float4*)&A[(size_t)(m0 + sr) * lda + k0 + sc + 16];
            a10 = *(const float4*)&A[(size_t)(m0 + sr + 64) * lda + k0 + sc];
            a11 = *(const float4*)&A[(size_t)(m0 + sr + 64) * lda + k0 + sc + 16];
            b00 = make_float4(0.f,0.f,0.f,0.f); b01 = b00; b10 = b00; b11 = b00;
            if (n0 + sr < N) {
                b00 = *(const float4*)&W[(size_t)(n0 + sr) * K + k0 + sc];
                b01 = *(const float4*)&W[(size_t)(n0 + sr) * K + k0 + sc + 16];
            }
            if (n0 + sr + 64 < N) {
                b10 = *(const float4*)&W[(size_t)(n0 + sr + 64) * K + k0 + sc];
                b11 = *(const float4*)&W[(size_t)(n0 + sr + 64) * K + k0 + sc + 16];
            }
        }

        const uint32_t bAH = base + (cur * BUF_W) * 4;
        const uint32_t bAL = bAH + TILE_W * 4;
        const uint32_t bBH = bAH + 2 * TILE_W * 4;
        const uint32_t bBL = bAH + 3 * TILE_W * 4;
#pragma unroll
        for (int kk = 0; kk < 2; ++kk) {
            uint32_t ah[4][4], al[4][4];
#pragma unroll
            for (int mt = 0; mt < 4; ++mt) {
                const uint32_t off = (((wm * 64 + mt * 16 + rA) * 20) + kk * 8 + cA) * 4;
                ldsm_x4(ah[mt], bAH + off);
                ldsm_x4(al[mt], bAL + off);
            }
            uint32_t bh[2][4], bl[2][4];
#pragma unroll
            for (int np = 0; np < 2; ++np) {
                const uint32_t off = (((wn * 32 + np * 16 + rB) * 20) + kk * 8 + cB) * 4;
                ldsm_x4(bh[np], bBH + off);
                ldsm_x4(bl[np], bBL + off);
            }
#pragma unroll
            for (int mt = 0; mt < 4; ++mt)
#pragma unroll
                for (int nt = 0; nt < 4; ++nt) {
                    const int np = nt >> 1, e0 = (nt & 1) * 2, e1 = e0 + 1;
                    mma_bf16(acc[mt][nt], ah[mt], bl[np][e0], bl[np][e1]);
                    mma_bf16(acc[mt][nt], al[mt], bh[np][e0], bh[np][e1]);
                    mma_bf16(acc[mt][nt], ah[mt], bh[np][e0], bh[np][e1]);
                }
        }

        if (more) {
            const int nxt = cur ^ 1;
            uint32_t* AH = sm + nxt * BUF_W; uint32_t* AL = AH + TILE_W;
            uint32_t* BH = AH + 2 * TILE_W;  uint32_t* BL = AH + 3 * TILE_W;
            split_store_bf(&AH[sr*20 + wc],          &AL[sr*20 + wc],          a00);
            split_store_bf(&AH[sr*20 + wc + 8],      &AL[sr*20 + wc + 8],      a01);
            split_store_bf(&AH[(sr+64)*20 + wc],     &AL[(sr+64)*20 + wc],     a10);
            split_store_bf(&AH[(sr+64)*20 + wc + 8], &AL[(sr+64)*20 + wc + 8], a11);
            split_store_bf(&BH[sr*20 + wc],          &BL[sr*20 + wc],          b00);
            split_store_bf(&BH[sr*20 + wc + 8],      &BL[sr*20 + wc + 8],      b01);
            split_store_bf(&BH[(sr+64)*20 + wc],     &BL[(sr+64)*20 + wc],     b10);
            split_store_bf(&BH[(sr+64)*20 + wc + 8], &BL[(sr+64)*20 + wc + 8], b11);
        }
        __syncthreads();
    }

    const int er = lane >> 2;
    const int ec = (lane & 3) * 2;
#pragma unroll
    for (int mt = 0; mt < 4; ++mt) {
        const int r0 = m0 + wm * 64 + mt * 16 + er;
#pragma unroll
        for (int nt = 0; nt < 4; ++nt) {
            const int cc = n0 + wn * 32 + nt * 8 + ec;
            if (cc >= N) continue;
            float v0 = acc[mt][nt][0], v1 = acc[mt][nt][1];
            float v2 = acc[mt][nt][2], v3 = acc[mt][nt][3];
            if (EP == 4) {
                const float bb0 = bias[cc], bb1 = bias[cc + 1];
                float vv[4] = {v0 + bb0, v1 + bb1, v2 + bb0, v3 + bb1};
                float dt[4], pp[4];
#pragma unroll
                for (int i = 0; i < 4; i++) {
                    float v = vv[i];
                    float e = __expf(-fabsf(v));
                    dt[i] = fmaxf(v, 0.f) + __logf(1.f + e);
                    pp[i] = __fdividef((v > 0.f ? e : 1.f), 1.f + e);
                }
                float4 o;
                o.x = dt[0]; o.y = pp[0]; o.z = dt[1]; o.w = pp[1];
                *(float4*)&C[2 * ((size_t)r0 * ldc + cc)] = o;
                o.x = dt[2]; o.y = pp[2]; o.z = dt[3]; o.w = pp[3];
                *(float4*)&C[2 * ((size_t)(r0 + 8) * ldc + cc)] = o;
            } else if (EP == 5) {
                const float bb0 = bias[cc], bb1 = bias[cc + 1];
                v0 += bb0; v1 += bb1; v2 += bb0; v3 += bb1;
                __nv_bfloat162 h01 = __floats2bfloat162_rn(v0, v1);
                __nv_bfloat162 h23 = __floats2bfloat162_rn(v2, v3);
                __nv_bfloat162 l01 = __floats2bfloat162_rn(
                    v0 - __bfloat162float(h01.x), v1 - __bfloat162float(h01.y));
                __nv_bfloat162 l23 = __floats2bfloat162_rn(
                    v2 - __bfloat162float(h23.x), v3 - __bfloat162float(h23.y));
                const size_t o0 = (size_t)r0 * ldc + cc;
                const size_t o1 = (size_t)(r0 + 8) * ldc + cc;
                *(__nv_bfloat162*)&Oh[o0] = h01;
                *(__nv_bfloat162*)&Ol[o0] = l01;
                *(__nv_bfloat162*)&Oh[o1] = h23;
                *(__nv_bfloat162*)&Ol[o1] = l23;
            } else {
                const size_t o0 = (size_t)r0 * ldc + cc;
                const size_t o1 = (size_t)(r0 + 8) * ldc + cc;
                float2 s;
                s.x = v0; s.y = v1; *(float2*)&C[o0] = s;
                s.x = v2; s.y = v3; *(float2*)&C[o1] = s;
            }
        }
    }
}

// ---------------- transposes -------------------------------------------------
__global__ void transpose_in_k(const float* __restrict__ in, float* __restrict__ inT)
{
    __shared__ float tile[32][33];
    int b  = blockIdx.z;
    int n0 = blockIdx.y * 32;
    int l0 = blockIdx.x * 32;
    int tx = threadIdx.x, ty = threadIdx.y;
    for (int i = ty; i < 32; i += 8)
        tile[i][tx] = in[(size_t)b * NUML * SEQ + (size_t)(n0 + i) * SEQ + l0 + tx];
    __syncthreads();
    for (int i = ty; i < 32; i += 8)
        inT[(size_t)(b * SEQ + l0 + i) * NUML + n0 + tx] = tile[tx][i];
}
__global__ void transpose_out_k(const float* __restrict__ Ct, float* __restrict__ out, int ld)
{
    __shared__ float tile[32][33];
    int b  = blockIdx.z;
    int l0 = blockIdx.x * 32;
    int p0 = blockIdx.y * 32;
    int tx = threadIdx.x, ty = threadIdx.y;
    for (int i = ty; i < 32; i += 8)
        tile[i][tx] = Ct[(size_t)(b * SEQ + l0 + i) * ld + p0 + tx];
    __syncthreads();
    for (int i = ty; i < 32; i += 8)
        out[(size_t)b * PREDL * SEQ + (size_t)(p0 + i) * SEQ + l0 + tx] = tile[tx][i];
}

// ---------------- depthwise conv + silu, 4 t-rows per thread ------------------
__global__ void conv_silu_k(const float* __restrict__ xz, const float* __restrict__ cw,
                            const float* __restrict__ cb, float* __restrict__ xc, int rev)
{
    const int i = blockIdx.x * blockDim.x + threadIdx.x;
    const int d4 = (i & 255) * 4;
    const int g  = i >> 8;
    const int t0 = (g & 255) * 4;
    const int b  = g >> 8;

    float4 w[4];
    w[0] = *(const float4*)&cw[(d4 + 0) * 4];
    w[1] = *(const float4*)&cw[(d4 + 1) * 4];
    w[2] = *(const float4*)&cw[(d4 + 2) * 4];
    w[3] = *(const float4*)&cw[(d4 + 3) * 4];
    const float4 bias = *(const float4*)&cb[d4];
    float4 out[4] = {bias, bias, bias, bias};

    const int jlo = rev ? 0 : -3;
#pragma unroll
    for (int jj = 0; jj < 7; jj++) {
        const int tt = t0 + jlo + jj;
        if ((unsigned)tt >= SEQ) continue;
        const float4 v = *(const float4*)&xz[(size_t)(b * SEQ + tt) * (2 * DINNER) + d4];
#pragma unroll
        for (int o = 0; o < 4; o++) {
            const int m = jj - o;
            if (m < 0 || m > 3) continue;
            const int k = rev ? (3 - m) : m;
            out[o].x = fmaf((&w[0].x)[k], v.x, out[o].x);
            out[o].y = fmaf((&w[1].x)[k], v.y, out[o].y);
            out[o].z = fmaf((&w[2].x)[k], v.z, out[o].z);
            out[o].w = fmaf((&w[3].x)[k], v.w, out[o].w);
        }
    }
#pragma unroll
    for (int o = 0; o < 4; o++) {
        float4 r = out[o];
        r.x = silu_f(r.x); r.y = silu_f(r.y);
        r.z = silu_f(r.z); r.w = silu_f(r.w);
        *(float4*)&xc[(size_t)(b * SEQ + t0 + o) * DINNER + d4] = r;
    }
}

// ---------------- selective scan, 4 lanes per (b,d), 4-deep prefetch ----------
__global__ void scan_k(const float2* __restrict__ dtp, const float* __restrict__ xcp,
                       const float* __restrict__ xdbl, const float* __restrict__ xz,
                       const float* __restrict__ a_log, const float* __restrict__ d_skip,
                       __nv_bfloat16* __restrict__ ysh, __nv_bfloat16* __restrict__ ysl,
                       int rev)
{
    int idx = blockIdx.x * blockDim.x + threadIdx.x;
    int q   = idx & 3;
    int gid = idx >> 2;
    int d = gid & (DINNER - 1);
    int b = gid >> 10;

    float A0 = -__expf(a_log[d * DSTATE + 4 * q + 0]);
    float A1 = -__expf(a_log[d * DSTATE + 4 * q + 1]);
    float A2 = -__expf(a_log[d * DSTATE + 4 * q + 2]);
    float A3 = -__expf(a_log[d * DSTATE + 4 * q + 3]);
    bool fast = fabsf(A0 + (4 * q + 1)) < 1e-4f && fabsf(A1 + (4 * q + 2)) < 1e-4f &&
                fabsf(A2 + (4 * q + 3)) < 1e-4f && fabsf(A3 + (4 * q + 4)) < 1e-4f;
    fast = __all_sync(0xffffffffu, fast);

    float h0 = 0.f, h1 = 0.f, h2 = 0.f, h3 = 0.f;
    const float Dp = d_skip[d];

    float2 dpb[4]; float xb[4]; float4 Bb[4], Cb[4]; float zb[4];
#pragma unroll
    for (int j = 0; j < 4; j++) {
        const int tt = rev ? (SEQ - 1 - j) : j;
        const size_t r = (size_t)b * SEQ + tt;
        dpb[j] = dtp[r * DINNER + d];
        xb[j]  = xcp[r * DINNER + d];
        Bb[j]  = *(const float4*)&xdbl[r * 64 + 32 + 4 * q];
        Cb[j]  = *(const float4*)&xdbl[r * 64 + 48 + 4 * q];
        zb[j]  = xz[r * (2 * DINNER) + DINNER + d];
    }

#pragma unroll 4
    for (int step = 0; step < SEQ; ++step) {
        const int j = step & 3;
        const int tc = rev ? (SEQ - 1 - step) : step;
        const size_t rc = (size_t)b * SEQ + tc;
        const float2 dpc = dpb[j];
        const float  xc_ = xb[j];
        const float4 Bc = Bb[j], Cc = Cb[j];
        const float  zc = zb[j];

        if (step + 4 < SEQ) {
            const int tn = rev ? (SEQ - 5 - step) : (step + 4);
            const size_t rn = (size_t)b * SEQ + tn;
            dpb[j] = dtp[rn * DINNER + d];
            xb[j]  = xcp[rn * DINNER + d];
            Bb[j]  = *(const float4*)&xdbl[rn * 64 + 32 + 4 * q];
            Cb[j]  = *(const float4*)&xdbl[rn * 64 + 48 + 4 * q];
            zb[j]  = xz[rn * (2 * DINNER) + DINNER + d];
        }

        const float dtx = dpc.x * xc_;
        float dA0, dA1, dA2, dA3;
        if (fast) {
            const float p  = dpc.y;
            const float p2 = p * p, p4 = p2 * p2, p8 = p4 * p4;
            float m = 1.f;
            if (q & 1) m = p4;
            if (q & 2) m *= p8;
            dA0 = m * p; dA1 = dA0 * p; dA2 = dA1 * p; dA3 = dA2 * p;
        } else {
            dA0 = __expf(dpc.x * A0); dA1 = __expf(dpc.x * A1);
            dA2 = __expf(dpc.x * A2); dA3 = __expf(dpc.x * A3);
        }
        h0 = fmaf(dA0, h0, dtx * Bc.x);
        h1 = fmaf(dA1, h1, dtx * Bc.y);
        h2 = fmaf(dA2, h2, dtx * Bc.z);
        h3 = fmaf(dA3, h3, dtx * Bc.w);
        float yp = (h0 * Cc.x + h1 * Cc.y) + (h2 * Cc.z + h3 * Cc.w);
        yp += __shfl_xor_sync(0xffffffffu, yp, 1);
        yp += __shfl_xor_sync(0xffffffffu, yp, 2);
        if (q == 0) {
            const float yv = (yp + xc_ * Dp) * silu_f(zc);
            const __nv_bfloat16 hb = __float2bfloat16_rn(yv);
            ysh[rc * DINNER + d] = hb;
            ysl[rc * DINNER + d] = __float2bfloat16_rn(yv - __bfloat162float(hb));
        }
    }
}

// ---------------- silu(a + a2) -> bf16 planes only ----------------------------
__global__ void silu3_k(const float4* __restrict__ a, const float4* __restrict__ a2,
                        __nv_bfloat16* __restrict__ h, __nv_bfloat16* __restrict__ l, int n4)
{
    int i = blockIdx.x * blockDim.x + threadIdx.x;
    if (i >= n4) return;
    float4 v = a[i];
    const float4 w = a2[i];
    v.x = silu_f(v.x + w.x); v.y = silu_f(v.y + w.y);
    v.z = silu_f(v.z + w.z); v.w = silu_f(v.w + w.w);
    __nv_bfloat162 h0 = __floats2bfloat162_rn(v.x, v.y);
    __nv_bfloat162 h1 = __floats2bfloat162_rn(v.z, v.w);
    __nv_bfloat162 l0 = __floats2bfloat162_rn(v.x - __bfloat162float(h0.x),
                                              v.y - __bfloat162float(h0.y));
    __nv_bfloat162 l1 = __floats2bfloat162_rn(v.z - __bfloat162float(h1.x),
                                              v.w - __bfloat162float(h1.y));
    ((__nv_bfloat162*)h)[i * 2]     = h0;
    ((__nv_bfloat162*)h)[i * 2 + 1] = h1;
    ((__nv_bfloat162*)l)[i * 2]     = l0;
    ((__nv_bfloat162*)l)[i * 2 + 1] = l1;
}

// ---------------- fp32 -> bf16 hi/lo split ------------------------------------
__global__ void split_k(const float* __restrict__ a, __nv_bfloat16* __restrict__ h,
                        __nv_bfloat16* __restrict__ l, int n)
{
    int i = blockIdx.x * blockDim.x + threadIdx.x;
    if (i >= n) return;
    const float v = a[i];
    const __nv_bfloat16 hb = __float2bfloat16_rn(v);
    h[i] = hb;
    l[i] = __float2bfloat16_rn(v - __bfloat162float(hb));
}

// w2 split with zero padding PREDL -> PREDP rows; also pads b2
__global__ void split_w2_k(const float* __restrict__ w2, const float* __restrict__ b2,
                           __nv_bfloat16* __restrict__ h, __nv_bfloat16* __restrict__ l,
                           float* __restrict__ b2p)
{
    int i = blockIdx.x * blockDim.x + threadIdx.x;
    if (i < PREDP) b2p[i] = (i < PREDL) ? b2[i] : 0.f;
    if (i >= PREDP * DMODEL) return;
    const int row = i >> 9;             // / DMODEL
    const float v = (row < PREDL) ? w2[i] : 0.f;
    const __nv_bfloat16 hb = __float2bfloat16_rn(v);
    h[i] = hb;
    l[i] = __float2bfloat16_rn(v - __bfloat162float(hb));
}

// ---------------- launcher ---------------------------------------------------
extern "C" void kernel_launch(void* const* d_in, const int* in_sizes, int n_in,
                              void* d_out, int out_size)
{
    (void)in_sizes; (void)n_in; (void)out_size;
    const float* inputs = (const float*)d_in[0];
    const float* w1     = (const float*)d_in[1];
    const float* b1     = (const float*)d_in[2];
    const float* w_in   = (const float*)d_in[3];
    const float* conv_w = (const float*)d_in[4];
    const float* conv_b = (const float*)d_in[5];
    const float* w_xp   = (const float*)d_in[6];
    const float* w_dt   = (const float*)d_in[7];
    const float* b_dt   = (const float*)d_in[8];
    const float* a_log  = (const float*)d_in[9];
    const float* d_skip = (const float*)d_in[10];
    const float* w_out  = (const float*)d_in[11];
    const float* w2     = (const float*)d_in[12];
    const float* b2     = (const float*)d_in[13];

    float *inT, *acc, *acc2, *xzA, *xzB, *xcA, *xcB, *xdA, *xdB, *dtA, *dtB, *fin, *b2p;
    __nv_bfloat16 *embh, *embl, *yshA, *yslA, *yshB, *yslB, *winh, *winl, *wouth, *woutl;
    __nv_bfloat16 *w2h, *w2l;
    cudaGetSymbolAddress((void**)&inT,   g_inT);
    cudaGetSymbolAddress((void**)&acc,   g_acc);
    cudaGetSymbolAddress((void**)&acc2,  g_acc2);
    cudaGetSymbolAddress((void**)&xzA,   g_xz);
    cudaGetSymbolAddress((void**)&xzB,   g_xz2);
    cudaGetSymbolAddress((void**)&xcA,   g_xc);
    cudaGetSymbolAddress((void**)&xcB,   g_xc2);
    cudaGetSymbolAddress((void**)&xdA,   g_xdbl);
    cudaGetSymbolAddress((void**)&xdB,   g_xdbl2);
    cudaGetSymbolAddress((void**)&dtA,   g_dtp);
    cudaGetSymbolAddress((void**)&dtB,   g_dtp2);
    cudaGetSymbolAddress((void**)&fin,   g_fin);
    cudaGetSymbolAddress((void**)&b2p,   g_b2p);
    cudaGetSymbolAddress((void**)&embh,  g_embh);
    cudaGetSymbolAddress((void**)&embl,  g_embl);
    cudaGetSymbolAddress((void**)&yshA,  g_ysh);
    cudaGetSymbolAddress((void**)&yslA,  g_ysl);
    cudaGetSymbolAddress((void**)&yshB,  g_ysh2);
    cudaGetSymbolAddress((void**)&yslB,  g_ysl2);
    cudaGetSymbolAddress((void**)&winh,  g_winh);
    cudaGetSymbolAddress((void**)&winl,  g_winl);
    cudaGetSymbolAddress((void**)&wouth, g_wouth);
    cudaGetSymbolAddress((void**)&woutl, g_woutl);
    cudaGetSymbolAddress((void**)&w2h,   g_w2h);
    cudaGetSymbolAddress((void**)&w2l,   g_w2l);

    cudaFuncSetAttribute(gemm_tc<0>, cudaFuncAttributeMaxDynamicSharedMemorySize, SMEM_BYT);
    cudaFuncSetAttribute(gemm_tc<4>, cudaFuncAttributeMaxDynamicSharedMemorySize, SMEM_BYT);
    cudaFuncSetAttribute(gemm_tc<5>, cudaFuncAttributeMaxDynamicSharedMemorySize, SMEM_BYT);
    cudaFuncSetAttribute(gemm_bf<0>, cudaFuncAttributeMaxDynamicSharedMemorySize, BF_SMEM);
    cudaFuncSetAttribute(gemm_bf<3>, cudaFuncAttributeMaxDynamicSharedMemorySize, BF_SMEM);

    // secondary stream + events (created once; no device memory)
    static cudaStream_t s2 = 0;
    static cudaEvent_t evF[2], evJ[2], evS, evW;
    if (!s2) {
        cudaStreamCreateWithFlags(&s2, cudaStreamNonBlocking);
        for (int i = 0; i < 2; i++) {
            cudaEventCreateWithFlags(&evF[i], cudaEventDisableTiming);
            cudaEventCreateWithFlags(&evJ[i], cudaEventDisableTiming);
        }
        cudaEventCreateWithFlags(&evS, cudaEventDisableTiming);
        cudaEventCreateWithFlags(&evW, cudaEventDisableTiming);
    }

    dim3 tb(32, 8);

    // fork: weight splits run on s2, overlapped with the embedding chain
    cudaEventRecord(evS, 0);
    cudaStreamWaitEvent(s2, evS, 0);
    split_k<<<(4*2*DINNER*DMODEL + 255)/256, 256, 0, s2>>>(
        w_in,  winh,  winl,  4*2*DINNER*DMODEL);
    split_k<<<(4*DMODEL*DINNER  + 255)/256, 256, 0, s2>>>(
        w_out, wouth, woutl, 4*DMODEL*DINNER);
    split_w2_k<<<(PREDP*DMODEL + 255)/256, 256, 0, s2>>>(w2, b2, w2h, w2l, b2p);
    cudaEventRecord(evW, s2);

    transpose_in_k<<<dim3(SEQ / 32, NUML / 32, BATCH), tb>>>(inputs, inT);
    // embedding GEMM with fused bias + bf16 hi/lo plane emit (EP=5)
    gemm_tc<5><<<dim3(DMODEL / 128, MROWS / 128), 256, SMEM_BYT>>>(
        inT, NUML, w1, b1, nullptr, DMODEL, DMODEL, NUML, embh, embl);

    // join: layer loop needs the split weights on both streams
    cudaStreamWaitEvent(0, evW, 0);

    for (int layer = 0; layer < 2; ++layer) {
        cudaEventRecord(evF[layer], 0);
        cudaStreamWaitEvent(s2, evF[layer], 0);

        for (int dir = 0; dir < 2; ++dir) {
            const int off = dir * 2 + layer;
            cudaStream_t st = dir ? s2 : 0;
            float* xz  = dir ? xzB : xzA;
            float* xc  = dir ? xcB : xcA;
            float* xd  = dir ? xdB : xdA;
            float* dtp = dir ? dtB : dtA;
            __nv_bfloat16* ysh = dir ? yshB : yshA;
            __nv_bfloat16* ysl = dir ? yslB : yslA;
            float* accD = dir ? acc2 : acc;

            const __nv_bfloat16* Winh = winh + (size_t)off * 2 * DINNER * DMODEL;
            const __nv_bfloat16* Winl = winl + (size_t)off * 2 * DINNER * DMODEL;
            const __nv_bfloat16* Wouh = wouth + (size_t)off * DMODEL * DINNER;
            const __nv_bfloat16* Woul = woutl + (size_t)off * DMODEL * DINNER;
            const float* cw   = conv_w + (size_t)off * DINNER * 4;
            const float* cb   = conv_b + (size_t)off * DINNER;
            const float* Wxp  = w_xp   + (size_t)off * 64 * DINNER;
            const float* Wdt  = w_dt   + (size_t)off * DINNER * DTRANK;
            const float* bdt  = b_dt   + (size_t)off * DINNER;
            const float* Al   = a_log  + (size_t)off * DINNER * DSTATE;
            const float* Dp   = d_skip + (size_t)off * DINNER;

            gemm_bf<0><<<dim3(2 * DINNER / 128, MROWS / 128), 256, BF_SMEM, st>>>(
                embh, embl, Winh, Winl, nullptr, xz, 2 * DINNER, DMODEL);

            conv_silu_k<<<(MROWS / 4) * (DINNER / 4) / 256, 256, 0, st>>>(xz, cw, cb, xc, dir);

            gemm_tc<0><<<dim3(1, MROWS / 128), 256, SMEM_BYT, st>>>(
                xc, DINNER, Wxp, nullptr, xd, 64, 64, DINNER, nullptr, nullptr);

            gemm_tc<4><<<dim3(DINNER / 128, MROWS / 128), 256, SMEM_BYT, st>>>(
                xd, 64, Wdt, bdt, dtp, DINNER, DINNER, DTRANK, nullptr, nullptr);

            scan_k<<<(BATCH * DINNER * 4) / 256, 256, 0, st>>>(
                (const float2*)dtp, xc, xd, xz, Al, Dp, ysh, ysl, dir);

            gemm_bf<0><<<dim3(DMODEL / 128, MROWS / 128), 256, BF_SMEM, st>>>(
                ysh, ysl, Wouh, Woul, nullptr, accD, DMODEL, DINNER);
        }

        cudaEventRecord(evJ[layer], s2);
        cudaStreamWaitEvent(0, evJ[layer], 0);

        silu3_k<<<(MROWS * DMODEL / 4 + 255) / 256, 256>>>(
            (const float4*)acc, (const float4*)acc2, embh, embl, MROWS * DMODEL / 4);
    }

    // final projection on bf16 planes with padded w2 (N=256, zero-padded rows)
    gemm_bf<3><<<dim3(PREDP / 128, MROWS / 128), 256, BF_SMEM>>>(
        embh, embl, w2h, w2l, b2p, fin, PREDP, DMODEL);

    transpose_out_k<<<dim3(SEQ / 32, PREDL / 32, BATCH), tb>>>(fin, (float*)d_out, PREDP);
}

// round 17
// speedup vs baseline: 1.0226x; 1.0011x over previous
#include <cuda_runtime.h>
#include <cuda_bf16.h>
#include <math.h>
#include <stdint.h>

#define BATCH  16
#define SEQ    1024
#define DMODEL 512
#define DINNER 1024
#define DTRANK 32
#define DSTATE 16
#define PREDL  192
#define PREDP  256              // padded PREDL for tile-aligned final GEMM
#define NUML   96
#define MROWS  (BATCH*SEQ)      // 16384

// ---------------- scratch (device globals; no allocations allowed) ----------
__device__ float g_inT [MROWS*NUML];
__device__ float g_acc [MROWS*DMODEL];
__device__ float g_acc2[MROWS*DMODEL];
__device__ float g_xz  [MROWS*2*DINNER];
__device__ float g_xz2 [MROWS*2*DINNER];
__device__ float g_xc  [MROWS*DINNER];
__device__ float g_xc2 [MROWS*DINNER];
__device__ float g_xdbl [MROWS*64];
__device__ float g_xdbl2[MROWS*64];
__device__ float g_dtp [MROWS*DINNER*2];   // interleaved (dt, exp(-dt))
__device__ float g_dtp2[MROWS*DINNER*2];
__device__ __nv_bfloat16 g_embh[MROWS*DMODEL];
__device__ __nv_bfloat16 g_embl[MROWS*DMODEL];
__device__ __nv_bfloat16 g_ysh [MROWS*DINNER];
__device__ __nv_bfloat16 g_ysl [MROWS*DINNER];
__device__ __nv_bfloat16 g_ysh2[MROWS*DINNER];
__device__ __nv_bfloat16 g_ysl2[MROWS*DINNER];
__device__ __nv_bfloat16 g_winh[4*2*DINNER*DMODEL];
__device__ __nv_bfloat16 g_winl[4*2*DINNER*DMODEL];
__device__ __nv_bfloat16 g_wouth[4*DMODEL*DINNER];
__device__ __nv_bfloat16 g_woutl[4*DMODEL*DINNER];
__device__ __nv_bfloat16 g_w2h [PREDP*DMODEL];
__device__ __nv_bfloat16 g_w2l [PREDP*DMODEL];
__device__ float g_b2p [PREDP];

__device__ __forceinline__ float silu_f(float x) {
    return x * (1.f / (1.f + __expf(-x)));
}

__device__ __forceinline__ void ldsm_x4(uint32_t (&r)[4], uint32_t addr) {
    asm volatile("ldmatrix.sync.aligned.m8n8.x4.shared.b16 {%0,%1,%2,%3}, [%4];"
                 : "=r"(r[0]), "=r"(r[1]), "=r"(r[2]), "=r"(r[3]) : "r"(addr));
}
__device__ __forceinline__ void mma_bf16(float (&c)[4], const uint32_t (&a)[4],
                                         uint32_t b0, uint32_t b1) {
    asm volatile("mma.sync.aligned.m16n8k16.row.col.f32.bf16.bf16.f32 "
                 "{%0,%1,%2,%3}, {%4,%5,%6,%7}, {%8,%9}, {%0,%1,%2,%3};"
                 : "+f"(c[0]), "+f"(c[1]), "+f"(c[2]), "+f"(c[3])
                 : "r"(a[0]), "r"(a[1]), "r"(a[2]), "r"(a[3]), "r"(b0), "r"(b1));
}
__device__ __forceinline__ void cpa16(uint32_t saddr, const void* g) {
    asm volatile("cp.async.cg.shared.global [%0], [%1], 16;"
                 :: "r"(saddr), "l"(g) : "memory");
}
#define CPA_COMMIT() asm volatile("cp.async.commit_group;" ::: "memory")
#define CPA_WAIT(n)  asm volatile("cp.async.wait_group %0;" :: "n"(n) : "memory")

// ============ pipelined bf16-plane GEMM:  C[M,N] = A @ W^T ===================
// 128x128 tile, BK=32, 3-stage cp.async, XOR-swizzled 16-word rows, 2 CTA/SM.
// EP: 0 = write, 4 = +bias, transposed store to out[b, p, l] (final proj).
#define BF_TILE_W  (128*16)
#define BF_STAGE_W (4*BF_TILE_W)
#define BF_SMEM    (3*BF_STAGE_W*4)  // 98304 B

template<int EP>
__global__ __launch_bounds__(256, 2) void gemm_bf(
    const __nv_bfloat16* __restrict__ Ah, const __nv_bfloat16* __restrict__ Al,
    const __nv_bfloat16* __restrict__ Wh, const __nv_bfloat16* __restrict__ Wl,
    const float* __restrict__ bias,
    float* __restrict__ C, int ldc, int K)
{
    extern __shared__ uint32_t sm[];
    const int t = threadIdx.x, lane = t & 31, warp = t >> 5;
    const int wm = warp >> 2, wn = warp & 3;
    const int m0 = blockIdx.y * 128, n0 = blockIdx.x * 128;
    const int nIt = K >> 5;
    const uint32_t base = (uint32_t)__cvta_generic_to_shared(&sm[0]);

    const int rA = ((lane >> 3) & 1) * 8 + (lane & 7);
    const int chA0 = (lane >> 4);
    const int rB = ((lane >> 4) & 1) * 8 + (lane & 7);
    const int chB0 = ((lane >> 3) & 1);

    float acc[4][4][4];
#pragma unroll
    for (int i = 0; i < 4; i++)
#pragma unroll
        for (int j = 0; j < 4; j++)
#pragma unroll
            for (int k = 0; k < 4; k++) acc[i][j][k] = 0.f;

    auto load_stage = [&](int s, int kb) {
        const uint32_t st = base + s * BF_STAGE_W * 4;
        const int koff = kb * 32;
#pragma unroll
        for (int i = 0; i < 8; i++) {
            const int c = t + i * 256;
            const int tile = c >> 9;
            const int w = c & 511;
            const int row = w >> 2;
            const int ch  = w & 3;
            const int chs = ch ^ ((row >> 1) & 3);
            const uint32_t sa = st + (tile * BF_TILE_W + row * 16 + chs * 4) * 4;
            const __nv_bfloat16* P = (tile == 0) ? Ah : (tile == 1) ? Al
                                   : (tile == 2) ? Wh : Wl;
            const int grow = ((tile < 2) ? m0 : n0) + row;
            cpa16(sa, P + (size_t)grow * K + koff + ch * 8);
        }
        CPA_COMMIT();
    };

    load_stage(0, 0);
    if (nIt > 1) load_stage(1, 1);

    for (int it = 0; it < nIt; ++it) {
        if (it + 2 < nIt) load_stage((it + 2) % 3, it + 2);
        if (it + 2 < nIt)      { CPA_WAIT(2); }
        else if (it + 1 < nIt) { CPA_WAIT(1); }
        else                   { CPA_WAIT(0); }
        __syncthreads();

        const uint32_t bAH = base + ((it % 3) * BF_STAGE_W) * 4;
        const uint32_t bAL = bAH + BF_TILE_W * 4;
        const uint32_t bBH = bAH + 2 * BF_TILE_W * 4;
        const uint32_t bBL = bAH + 3 * BF_TILE_W * 4;
#pragma unroll
        for (int kk = 0; kk < 2; ++kk) {
            uint32_t bh[2][4], bl[2][4];
            const int chB = kk * 2 + chB0;
#pragma unroll
            for (int np = 0; np < 2; ++np) {
                const int rowB = wn * 32 + np * 16 + rB;
                const uint32_t off = (rowB * 16 + ((chB ^ ((rowB >> 1) & 3)) * 4)) * 4;
                ldsm_x4(bh[np], bBH + off);
                ldsm_x4(bl[np], bBL + off);
            }
            const int chA = kk * 2 + chA0;
#pragma unroll
            for (int mt = 0; mt < 4; ++mt) {
                const int rowA = wm * 64 + mt * 16 + rA;
                const uint32_t off = (rowA * 16 + ((chA ^ ((rowA >> 1) & 3)) * 4)) * 4;
                uint32_t ah[4];
                ldsm_x4(ah, bAH + off);
#pragma unroll
                for (int nt = 0; nt < 4; ++nt) {
                    const int np = nt >> 1, e0 = (nt & 1) * 2, e1 = e0 + 1;
                    mma_bf16(acc[mt][nt], ah, bh[np][e0], bh[np][e1]);
                    mma_bf16(acc[mt][nt], ah, bl[np][e0], bl[np][e1]);
                }
                uint32_t al[4];
                ldsm_x4(al, bAL + off);
#pragma unroll
                for (int nt = 0; nt < 4; ++nt) {
                    const int np = nt >> 1, e0 = (nt & 1) * 2, e1 = e0 + 1;
                    mma_bf16(acc[mt][nt], al, bh[np][e0], bh[np][e1]);
                }
            }
        }
        __syncthreads();
    }

    const int er = lane >> 2;
    const int ec = (lane & 3) * 2;

    if (EP == 4) {
        // transposed epilogue: stage tile as ts[col][row] then coalesced out stores
        __syncthreads();
        float* ts = (float*)sm;              // [128 cols][132 row-stride]
#pragma unroll
        for (int mt = 0; mt < 4; ++mt) {
            const int rl0 = wm * 64 + mt * 16 + er;
#pragma unroll
            for (int nt = 0; nt < 4; ++nt) {
                const int cl = wn * 32 + nt * 8 + ec;
                const float bb0 = bias[n0 + cl], bb1 = bias[n0 + cl + 1];
                ts[cl * 132 + rl0]           = acc[mt][nt][0] + bb0;
                ts[(cl + 1) * 132 + rl0]     = acc[mt][nt][1] + bb1;
                ts[cl * 132 + rl0 + 8]       = acc[mt][nt][2] + bb0;
                ts[(cl + 1) * 132 + rl0 + 8] = acc[mt][nt][3] + bb1;
            }
        }
        __syncthreads();
        const int b  = m0 >> 10;             // / SEQ
        const int l0 = m0 & (SEQ - 1);
        const int pmax = (n0 + 128 <= PREDL) ? 128 : (PREDL > n0 ? PREDL - n0 : 0);
        for (int idx = t; idx < pmax * 32; idx += 256) {
            const int p  = idx >> 5;
            const int l4 = (idx & 31) * 4;
            const float4 v = *(const float4*)&ts[p * 132 + l4];
            *(float4*)&C[(size_t)b * PREDL * SEQ + (size_t)(n0 + p) * SEQ + l0 + l4] = v;
        }
        return;
    }

#pragma unroll
    for (int mt = 0; mt < 4; ++mt) {
        const int r0 = m0 + wm * 64 + mt * 16 + er;
#pragma unroll
        for (int nt = 0; nt < 4; ++nt) {
            const int cc = n0 + wn * 32 + nt * 8 + ec;
            float v0 = acc[mt][nt][0], v1 = acc[mt][nt][1];
            float v2 = acc[mt][nt][2], v3 = acc[mt][nt][3];
            const size_t o0 = (size_t)r0 * ldc + cc;
            const size_t o1 = (size_t)(r0 + 8) * ldc + cc;
            float2 s;
            s.x = v0; s.y = v1; *(float2*)&C[o0] = s;
            s.x = v2; s.y = v3; *(float2*)&C[o1] = s;
        }
    }
}

// ====================== fp32-input mma.sync GEMM (small shapes) ==============
__device__ __forceinline__ void split_store_bf(uint32_t* hiP, uint32_t* loP, float4 v) {
    __nv_bfloat162 h0 = __floats2bfloat162_rn(v.x, v.y);
    __nv_bfloat162 h1 = __floats2bfloat162_rn(v.z, v.w);
    float lx = v.x - __bfloat162float(h0.x);
    float ly = v.y - __bfloat162float(h0.y);
    float lz = v.z - __bfloat162float(h1.x);
    float lw = v.w - __bfloat162float(h1.y);
    __nv_bfloat162 l0 = __floats2bfloat162_rn(lx, ly);
    __nv_bfloat162 l1 = __floats2bfloat162_rn(lz, lw);
    uint2 hu, lu;
    hu.x = *(uint32_t*)&h0; hu.y = *(uint32_t*)&h1;
    lu.x = *(uint32_t*)&l0; lu.y = *(uint32_t*)&l1;
    *(uint2*)hiP = hu;
    *(uint2*)loP = lu;
}

#define TILE_W   (128*20)
#define BUF_W    (4*TILE_W)
#define SMEM_BYT (2*BUF_W*4)   // 81920

// EP: 0 = none, 4 = +bias softplus (dt, exp(-dt)), 5 = +bias, split to bf16 planes
template<int EP>
__global__ __launch_bounds__(256) void gemm_tc(
    const float* __restrict__ A, int lda,
    const float* __restrict__ W,
    const float* __restrict__ bias,
    float* __restrict__ C, int ldc,
    int N, int K,
    __nv_bfloat16* __restrict__ Oh, __nv_bfloat16* __restrict__ Ol)
{
    extern __shared__ uint32_t sm[];

    const int t    = threadIdx.x;
    const int lane = t & 31, warp = t >> 5;
    const int wm   = warp >> 2, wn = warp & 3;
    const int m0   = blockIdx.y * 128, n0 = blockIdx.x * 128;

    const int sr = t >> 2;
    const int sc = (t & 3) * 4;

    const int rA = ((lane >> 3) & 1) * 8 + (lane & 7);
    const int cA = (lane >> 4) * 4;
    const int rB = ((lane >> 4) & 1) * 8 + (lane & 7);
    const int cB = ((lane >> 3) & 1) * 4;

    float acc[4][4][4];
#pragma unroll
    for (int i = 0; i < 4; i++)
#pragma unroll
        for (int j = 0; j < 4; j++)
#pragma unroll
            for (int k = 0; k < 4; k++) acc[i][j][k] = 0.f;

    const int nIt = K >> 5;
    const uint32_t base = (uint32_t)__cvta_generic_to_shared(&sm[0]);
    const int wc = sc >> 1;

    float4 a00, a01, a10, a11, b00, b01, b10, b11;
    {
        a00 = *(const float4*)&A[(size_t)(m0 + sr) * lda + sc];
        a01 = *(const float4*)&A[(size_t)(m0 + sr) * lda + sc + 16];
        a10 = *(const float4*)&A[(size_t)(m0 + sr + 64) * lda + sc];
        a11 = *(const float4*)&A[(size_t)(m0 + sr + 64) * lda + sc + 16];
        b00 = make_float4(0.f,0.f,0.f,0.f); b01 = b00; b10 = b00; b11 = b00;
        if (n0 + sr < N) {
            b00 = *(const float4*)&W[(size_t)(n0 + sr) * K + sc];
            b01 = *(const float4*)&W[(size_t)(n0 + sr) * K + sc + 16];
        }
        if (n0 + sr + 64 < N) {
            b10 = *(const float4*)&W[(size_t)(n0 + sr + 64) * K + sc];
            b11 = *(const float4*)&W[(size_t)(n0 + sr + 64) * K + sc + 16];
        }
        uint32_t* AH = sm;              uint32_t* AL = sm + TILE_W;
        uint32_t* BH = sm + 2 * TILE_W; uint32_t* BL = sm + 3 * TILE_W;
        split_store_bf(&AH[sr*20 + wc],            &AL[sr*20 + wc],            a00);
        split_store_bf(&AH[sr*20 + wc + 8],        &AL[sr*20 + wc + 8],        a01);
        split_store_bf(&AH[(sr+64)*20 + wc],       &AL[(sr+64)*20 + wc],       a10);
        split_store_bf(&AH[(sr+64)*20 + wc + 8],   &AL[(sr+64)*20 + wc + 8],   a11);
        split_store_bf(&BH[sr*20 + wc],            &BL[sr*20 + wc],            b00);
        split_store_bf(&BH[sr*20 + wc + 8],        &BL[sr*20 + wc + 8],        b01);
        split_store_bf(&BH[(sr+64)*20 + wc],       &BL[(sr+64)*20 + wc],       b10);
        split_store_bf(&BH[(sr+64)*20 + wc + 8],   &BL[(sr+64)*20 + wc + 8],   b11);
    }
    __syncthreads();

    for (int it = 0; it < nIt; ++it) {
        const int cur = it & 1;
        const bool more = (it + 1 < nIt);
        if (more) {
            int k0 = (it + 1) << 5;
            a00 = *(const float4*)&A[(size_t)(m0 + sr) * lda + k0 + sc];
            a01 = *(const float4*)&A[(size_t)(m0 + sr) * lda + k0 + sc + 16];
            a10 = *(const float4*)&A[(size_t)(m0 + sr + 64) * lda + k0 + sc];
            a11 = *(const float4*)&A[(size_t)(m0 + sr + 64) * lda + k0 + sc + 16];
            b00 = make_float4(0.f,0.f,0.f,0.f); b01 = b00; b10 = b00; b11 = b00;
            if (n0 + sr < N) {
                b00 = *(const float4*)&W[(size_t)(n0 + sr) * K + k0 + sc];
                b01 = *(const float4*)&W[(size_t)(n0 + sr) * K + k0 + sc + 16];
            }
            if (n0 + sr + 64 < N) {
                b10 = *(const float4*)&W[(size_t)(n0 + sr + 64) * K + k0 + sc];
                b11 = *(const float4*)&W[(size_t)(n0 + sr + 64) * K + k0 + sc + 16];
            }
        }

        const uint32_t bAH = base + (cur * BUF_W) * 4;
        const uint32_t bAL = bAH + TILE_W * 4;
        const uint32_t bBH = bAH + 2 * TILE_W * 4;
        const uint32_t bBL = bAH + 3 * TILE_W * 4;
#pragma unroll
        for (int kk = 0; kk < 2; ++kk) {
            uint32_t ah[4][4], al[4][4];
#pragma unroll
            for (int mt = 0; mt < 4; ++mt) {
                const uint32_t off = (((wm * 64 + mt * 16 + rA) * 20) + kk * 8 + cA) * 4;
                ldsm_x4(ah[mt], bAH + off);
                ldsm_x4(al[mt], bAL + off);
            }
            uint32_t bh[2][4], bl[2][4];
#pragma unroll
            for (int np = 0; np < 2; ++np) {
                const uint32_t off = (((wn * 32 + np * 16 + rB) * 20) + kk * 8 + cB) * 4;
                ldsm_x4(bh[np], bBH + off);
                ldsm_x4(bl[np], bBL + off);
            }
#pragma unroll
            for (int mt = 0; mt < 4; ++mt)
#pragma unroll
                for (int nt = 0; nt < 4; ++nt) {
                    const int np = nt >> 1, e0 = (nt & 1) * 2, e1 = e0 + 1;
                    mma_bf16(acc[mt][nt], ah[mt], bl[np][e0], bl[np][e1]);
                    mma_bf16(acc[mt][nt], al[mt], bh[np][e0], bh[np][e1]);
                    mma_bf16(acc[mt][nt], ah[mt], bh[np][e0], bh[np][e1]);
                }
        }

        if (more) {
            const int nxt = cur ^ 1;
            uint32_t* AH = sm + nxt * BUF_W; uint32_t* AL = AH + TILE_W;
            uint32_t* BH = AH + 2 * TILE_W;  uint32_t* BL = AH + 3 * TILE_W;
            split_store_bf(&AH[sr*20 + wc],          &AL[sr*20 + wc],          a00);
            split_store_bf(&AH[sr*20 + wc + 8],      &AL[sr*20 + wc + 8],      a01);
            split_store_bf(&AH[(sr+64)*20 + wc],     &AL[(sr+64)*20 + wc],     a10);
            split_store_bf(&AH[(sr+64)*20 + wc + 8], &AL[(sr+64)*20 + wc + 8], a11);
            split_store_bf(&BH[sr*20 + wc],          &BL[sr*20 + wc],          b00);
            split_store_bf(&BH[sr*20 + wc + 8],      &BL[sr*20 + wc + 8],      b01);
            split_store_bf(&BH[(sr+64)*20 + wc],     &BL[(sr+64)*20 + wc],     b10);
            split_store_bf(&BH[(sr+64)*20 + wc + 8], &BL[(sr+64)*20 + wc + 8], b11);
        }
        __syncthreads();
    }

    const int er = lane >> 2;
    const int ec = (lane & 3) * 2;
#pragma unroll
    for (int mt = 0; mt < 4; ++mt) {
        const int r0 = m0 + wm * 64 + mt * 16 + er;
#pragma unroll
        for (int nt = 0; nt < 4; ++nt) {
            const int cc = n0 + wn * 32 + nt * 8 + ec;
            if (cc >= N) continue;
            float v0 = acc[mt][nt][0], v1 = acc[mt][nt][1];
            float v2 = acc[mt][nt][2], v3 = acc[mt][nt][3];
            if (EP == 4) {
                const float bb0 = bias[cc], bb1 = bias[cc + 1];
                float vv[4] = {v0 + bb0, v1 + bb1, v2 + bb0, v3 + bb1};
                float dt[4], pp[4];
#pragma unroll
                for (int i = 0; i < 4; i++) {
                    float v = vv[i];
                    float e = __expf(-fabsf(v));
                    dt[i] = fmaxf(v, 0.f) + __logf(1.f + e);
                    pp[i] = __fdividef((v > 0.f ? e : 1.f), 1.f + e);
                }
                float4 o;
                o.x = dt[0]; o.y = pp[0]; o.z = dt[1]; o.w = pp[1];
                *(float4*)&C[2 * ((size_t)r0 * ldc + cc)] = o;
                o.x = dt[2]; o.y = pp[2]; o.z = dt[3]; o.w = pp[3];
                *(float4*)&C[2 * ((size_t)(r0 + 8) * ldc + cc)] = o;
            } else if (EP == 5) {
                const float bb0 = bias[cc], bb1 = bias[cc + 1];
                v0 += bb0; v1 += bb1; v2 += bb0; v3 += bb1;
                __nv_bfloat162 h01 = __floats2bfloat162_rn(v0, v1);
                __nv_bfloat162 h23 = __floats2bfloat162_rn(v2, v3);
                __nv_bfloat162 l01 = __floats2bfloat162_rn(
                    v0 - __bfloat162float(h01.x), v1 - __bfloat162float(h01.y));
                __nv_bfloat162 l23 = __floats2bfloat162_rn(
                    v2 - __bfloat162float(h23.x), v3 - __bfloat162float(h23.y));
                const size_t o0 = (size_t)r0 * ldc + cc;
                const size_t o1 = (size_t)(r0 + 8) * ldc + cc;
                *(__nv_bfloat162*)&Oh[o0] = h01;
                *(__nv_bfloat162*)&Ol[o0] = l01;
                *(__nv_bfloat162*)&Oh[o1] = h23;
                *(__nv_bfloat162*)&Ol[o1] = l23;
            } else {
                const size_t o0 = (size_t)r0 * ldc + cc;
                const size_t o1 = (size_t)(r0 + 8) * ldc + cc;
                float2 s;
                s.x = v0; s.y = v1; *(float2*)&C[o0] = s;
                s.x = v2; s.y = v3; *(float2*)&C[o1] = s;
            }
        }
    }
}

// ---------------- input transpose ---------------------------------------------
__global__ void transpose_in_k(const float* __restrict__ in, float* __restrict__ inT)
{
    __shared__ float tile[32][33];
    int b  = blockIdx.z;
    int n0 = blockIdx.y * 32;
    int l0 = blockIdx.x * 32;
    int tx = threadIdx.x, ty = threadIdx.y;
    for (int i = ty; i < 32; i += 8)
        tile[i][tx] = in[(size_t)b * NUML * SEQ + (size_t)(n0 + i) * SEQ + l0 + tx];
    __syncthreads();
    for (int i = ty; i < 32; i += 8)
        inT[(size_t)(b * SEQ + l0 + i) * NUML + n0 + tx] = tile[tx][i];
}

// ---------------- depthwise conv + silu, 4 t-rows per thread ------------------
__global__ void conv_silu_k(const float* __restrict__ xz, const float* __restrict__ cw,
                            const float* __restrict__ cb, float* __restrict__ xc, int rev)
{
    const int i = blockIdx.x * blockDim.x + threadIdx.x;
    const int d4 = (i & 255) * 4;
    const int g  = i >> 8;
    const int t0 = (g & 255) * 4;
    const int b  = g >> 8;

    float4 w[4];
    w[0] = *(const float4*)&cw[(d4 + 0) * 4];
    w[1] = *(const float4*)&cw[(d4 + 1) * 4];
    w[2] = *(const float4*)&cw[(d4 + 2) * 4];
    w[3] = *(const float4*)&cw[(d4 + 3) * 4];
    const float4 bias = *(const float4*)&cb[d4];
    float4 out[4] = {bias, bias, bias, bias};

    const int jlo = rev ? 0 : -3;
#pragma unroll
    for (int jj = 0; jj < 7; jj++) {
        const int tt = t0 + jlo + jj;
        if ((unsigned)tt >= SEQ) continue;
        const float4 v = *(const float4*)&xz[(size_t)(b * SEQ + tt) * (2 * DINNER) + d4];
#pragma unroll
        for (int o = 0; o < 4; o++) {
            const int m = jj - o;
            if (m < 0 || m > 3) continue;
            const int k = rev ? (3 - m) : m;
            out[o].x = fmaf((&w[0].x)[k], v.x, out[o].x);
            out[o].y = fmaf((&w[1].x)[k], v.y, out[o].y);
            out[o].z = fmaf((&w[2].x)[k], v.z, out[o].z);
            out[o].w = fmaf((&w[3].x)[k], v.w, out[o].w);
        }
    }
#pragma unroll
    for (int o = 0; o < 4; o++) {
        float4 r = out[o];
        r.x = silu_f(r.x); r.y = silu_f(r.y);
        r.z = silu_f(r.z); r.w = silu_f(r.w);
        *(float4*)&xc[(size_t)(b * SEQ + t0 + o) * DINNER + d4] = r;
    }
}

// ---------------- selective scan, 4 lanes per (b,d), 4-deep prefetch ----------
__global__ void scan_k(const float2* __restrict__ dtp, const float* __restrict__ xcp,
                       const float* __restrict__ xdbl, const float* __restrict__ xz,
                       const float* __restrict__ a_log, const float* __restrict__ d_skip,
                       __nv_bfloat16* __restrict__ ysh, __nv_bfloat16* __restrict__ ysl,
                       int rev)
{
    int idx = blockIdx.x * blockDim.x + threadIdx.x;
    int q   = idx & 3;
    int gid = idx >> 2;
    int d = gid & (DINNER - 1);
    int b = gid >> 10;

    float A0 = -__expf(a_log[d * DSTATE + 4 * q + 0]);
    float A1 = -__expf(a_log[d * DSTATE + 4 * q + 1]);
    float A2 = -__expf(a_log[d * DSTATE + 4 * q + 2]);
    float A3 = -__expf(a_log[d * DSTATE + 4 * q + 3]);
    bool fast = fabsf(A0 + (4 * q + 1)) < 1e-4f && fabsf(A1 + (4 * q + 2)) < 1e-4f &&
                fabsf(A2 + (4 * q + 3)) < 1e-4f && fabsf(A3 + (4 * q + 4)) < 1e-4f;
    fast = __all_sync(0xffffffffu, fast);

    float h0 = 0.f, h1 = 0.f, h2 = 0.f, h3 = 0.f;
    const float Dp = d_skip[d];

    float2 dpb[4]; float xb[4]; float4 Bb[4], Cb[4]; float zb[4];
#pragma unroll
    for (int j = 0; j < 4; j++) {
        const int tt = rev ? (SEQ - 1 - j) : j;
        const size_t r = (size_t)b * SEQ + tt;
        dpb[j] = dtp[r * DINNER + d];
        xb[j]  = xcp[r * DINNER + d];
        Bb[j]  = *(const float4*)&xdbl[r * 64 + 32 + 4 * q];
        Cb[j]  = *(const float4*)&xdbl[r * 64 + 48 + 4 * q];
        zb[j]  = xz[r * (2 * DINNER) + DINNER + d];
    }

#pragma unroll 4
    for (int step = 0; step < SEQ; ++step) {
        const int j = step & 3;
        const int tc = rev ? (SEQ - 1 - step) : step;
        const size_t rc = (size_t)b * SEQ + tc;
        const float2 dpc = dpb[j];
        const float  xc_ = xb[j];
        const float4 Bc = Bb[j], Cc = Cb[j];
        const float  zc = zb[j];

        if (step + 4 < SEQ) {
            const int tn = rev ? (SEQ - 5 - step) : (step + 4);
            const size_t rn = (size_t)b * SEQ + tn;
            dpb[j] = dtp[rn * DINNER + d];
            xb[j]  = xcp[rn * DINNER + d];
            Bb[j]  = *(const float4*)&xdbl[rn * 64 + 32 + 4 * q];
            Cb[j]  = *(const float4*)&xdbl[rn * 64 + 48 + 4 * q];
            zb[j]  = xz[rn * (2 * DINNER) + DINNER + d];
        }

        const float dtx = dpc.x * xc_;
        float dA0, dA1, dA2, dA3;
        if (fast) {
            const float p  = dpc.y;
            const float p2 = p * p, p4 = p2 * p2, p8 = p4 * p4;
            float m = 1.f;
            if (q & 1) m = p4;
            if (q & 2) m *= p8;
            dA0 = m * p; dA1 = dA0 * p; dA2 = dA1 * p; dA3 = dA2 * p;
        } else {
            dA0 = __expf(dpc.x * A0); dA1 = __expf(dpc.x * A1);
            dA2 = __expf(dpc.x * A2); dA3 = __expf(dpc.x * A3);
        }
        h0 = fmaf(dA0, h0, dtx * Bc.x);
        h1 = fmaf(dA1, h1, dtx * Bc.y);
        h2 = fmaf(dA2, h2, dtx * Bc.z);
        h3 = fmaf(dA3, h3, dtx * Bc.w);
        float yp = (h0 * Cc.x + h1 * Cc.y) + (h2 * Cc.z + h3 * Cc.w);
        yp += __shfl_xor_sync(0xffffffffu, yp, 1);
        yp += __shfl_xor_sync(0xffffffffu, yp, 2);
        if (q == 0) {
            const float yv = (yp + xc_ * Dp) * silu_f(zc);
            const __nv_bfloat16 hb = __float2bfloat16_rn(yv);
            ysh[rc * DINNER + d] = hb;
            ysl[rc * DINNER + d] = __float2bfloat16_rn(yv - __bfloat162float(hb));
        }
    }
}

// ---------------- silu(a + a2) -> bf16 planes only ----------------------------
__global__ void silu3_k(const float4* __restrict__ a, const float4* __restrict__ a2,
                        __nv_bfloat16* __restrict__ h, __nv_bfloat16* __restrict__ l, int n4)
{
    int i = blockIdx.x * blockDim.x + threadIdx.x;
    if (i >= n4) return;
    float4 v = a[i];
    const float4 w = a2[i];
    v.x = silu_f(v.x + w.x); v.y = silu_f(v.y + w.y);
    v.z = silu_f(v.z + w.z); v.w = silu_f(v.w + w.w);
    __nv_bfloat162 h0 = __floats2bfloat162_rn(v.x, v.y);
    __nv_bfloat162 h1 = __floats2bfloat162_rn(v.z, v.w);
    __nv_bfloat162 l0 = __floats2bfloat162_rn(v.x - __bfloat162float(h0.x),
                                              v.y - __bfloat162float(h0.y));
    __nv_bfloat162 l1 = __floats2bfloat162_rn(v.z - __bfloat162float(h1.x),
                                              v.w - __bfloat162float(h1.y));
    ((__nv_bfloat162*)h)[i * 2]     = h0;
    ((__nv_bfloat162*)h)[i * 2 + 1] = h1;
    ((__nv_bfloat162*)l)[i * 2]     = l0;
    ((__nv_bfloat162*)l)[i * 2 + 1] = l1;
}

// ---------------- fp32 -> bf16 hi/lo split ------------------------------------
__global__ void split_k(const float* __restrict__ a, __nv_bfloat16* __restrict__ h,
                        __nv_bfloat16* __restrict__ l, int n)
{
    int i = blockIdx.x * blockDim.x + threadIdx.x;
    if (i >= n) return;
    const float v = a[i];
    const __nv_bfloat16 hb = __float2bfloat16_rn(v);
    h[i] = hb;
    l[i] = __float2bfloat16_rn(v - __bfloat162float(hb));
}

// w2 split with zero padding PREDL -> PREDP rows; also pads b2
__global__ void split_w2_k(const float* __restrict__ w2, const float* __restrict__ b2,
                           __nv_bfloat16* __restrict__ h, __nv_bfloat16* __restrict__ l,
                           float* __restrict__ b2p)
{
    int i = blockIdx.x * blockDim.x + threadIdx.x;
    if (i < PREDP) b2p[i] = (i < PREDL) ? b2[i] : 0.f;
    if (i >= PREDP * DMODEL) return;
    const int row = i >> 9;             // / DMODEL
    const float v = (row < PREDL) ? w2[i] : 0.f;
    const __nv_bfloat16 hb = __float2bfloat16_rn(v);
    h[i] = hb;
    l[i] = __float2bfloat16_rn(v - __bfloat162float(hb));
}

// ---------------- launcher ---------------------------------------------------
extern "C" void kernel_launch(void* const* d_in, const int* in_sizes, int n_in,
                              void* d_out, int out_size)
{
    (void)in_sizes; (void)n_in; (void)out_size;
    const float* inputs = (const float*)d_in[0];
    const float* w1     = (const float*)d_in[1];
    const float* b1     = (const float*)d_in[2];
    const float* w_in   = (const float*)d_in[3];
    const float* conv_w = (const float*)d_in[4];
    const float* conv_b = (const float*)d_in[5];
    const float* w_xp   = (const float*)d_in[6];
    const float* w_dt   = (const float*)d_in[7];
    const float* b_dt   = (const float*)d_in[8];
    const float* a_log  = (const float*)d_in[9];
    const float* d_skip = (const float*)d_in[10];
    const float* w_out  = (const float*)d_in[11];
    const float* w2     = (const float*)d_in[12];
    const float* b2     = (const float*)d_in[13];

    float *inT, *acc, *acc2, *xzA, *xzB, *xcA, *xcB, *xdA, *xdB, *dtA, *dtB, *b2p;
    __nv_bfloat16 *embh, *embl, *yshA, *yslA, *yshB, *yslB, *winh, *winl, *wouth, *woutl;
    __nv_bfloat16 *w2h, *w2l;
    cudaGetSymbolAddress((void**)&inT,   g_inT);
    cudaGetSymbolAddress((void**)&acc,   g_acc);
    cudaGetSymbolAddress((void**)&acc2,  g_acc2);
    cudaGetSymbolAddress((void**)&xzA,   g_xz);
    cudaGetSymbolAddress((void**)&xzB,   g_xz2);
    cudaGetSymbolAddress((void**)&xcA,   g_xc);
    cudaGetSymbolAddress((void**)&xcB,   g_xc2);
    cudaGetSymbolAddress((void**)&xdA,   g_xdbl);
    cudaGetSymbolAddress((void**)&xdB,   g_xdbl2);
    cudaGetSymbolAddress((void**)&dtA,   g_dtp);
    cudaGetSymbolAddress((void**)&dtB,   g_dtp2);
    cudaGetSymbolAddress((void**)&b2p,   g_b2p);
    cudaGetSymbolAddress((void**)&embh,  g_embh);
    cudaGetSymbolAddress((void**)&embl,  g_embl);
    cudaGetSymbolAddress((void**)&yshA,  g_ysh);
    cudaGetSymbolAddress((void**)&yslA,  g_ysl);
    cudaGetSymbolAddress((void**)&yshB,  g_ysh2);
    cudaGetSymbolAddress((void**)&yslB,  g_ysl2);
    cudaGetSymbolAddress((void**)&winh,  g_winh);
    cudaGetSymbolAddress((void**)&winl,  g_winl);
    cudaGetSymbolAddress((void**)&wouth, g_wouth);
    cudaGetSymbolAddress((void**)&woutl, g_woutl);
    cudaGetSymbolAddress((void**)&w2h,   g_w2h);
    cudaGetSymbolAddress((void**)&w2l,   g_w2l);

    cudaFuncSetAttribute(gemm_tc<0>, cudaFuncAttributeMaxDynamicSharedMemorySize, SMEM_BYT);
    cudaFuncSetAttribute(gemm_tc<4>, cudaFuncAttributeMaxDynamicSharedMemorySize, SMEM_BYT);
    cudaFuncSetAttribute(gemm_tc<5>, cudaFuncAttributeMaxDynamicSharedMemorySize, SMEM_BYT);
    cudaFuncSetAttribute(gemm_bf<0>, cudaFuncAttributeMaxDynamicSharedMemorySize, BF_SMEM);
    cudaFuncSetAttribute(gemm_bf<4>, cudaFuncAttributeMaxDynamicSharedMemorySize, BF_SMEM);

    // secondary stream + events (created once; no device memory)
    static cudaStream_t s2 = 0;
    static cudaEvent_t evF[2], evJ[2], evS, evW;
    if (!s2) {
        cudaStreamCreateWithFlags(&s2, cudaStreamNonBlocking);
        for (int i = 0; i < 2; i++) {
            cudaEventCreateWithFlags(&evF[i], cudaEventDisableTiming);
            cudaEventCreateWithFlags(&evJ[i], cudaEventDisableTiming);
        }
        cudaEventCreateWithFlags(&evS, cudaEventDisableTiming);
        cudaEventCreateWithFlags(&evW, cudaEventDisableTiming);
    }

    dim3 tb(32, 8);

    // fork: weight splits run on s2, overlapped with the embedding chain
    cudaEventRecord(evS, 0);
    cudaStreamWaitEvent(s2, evS, 0);
    split_k<<<(4*2*DINNER*DMODEL + 255)/256, 256, 0, s2>>>(
        w_in,  winh,  winl,  4*2*DINNER*DMODEL);
    split_k<<<(4*DMODEL*DINNER  + 255)/256, 256, 0, s2>>>(
        w_out, wouth, woutl, 4*DMODEL*DINNER);
    split_w2_k<<<(PREDP*DMODEL + 255)/256, 256, 0, s2>>>(w2, b2, w2h, w2l, b2p);
    cudaEventRecord(evW, s2);

    transpose_in_k<<<dim3(SEQ / 32, NUML / 32, BATCH), tb>>>(inputs, inT);
    // embedding GEMM with fused bias + bf16 hi/lo plane emit (EP=5)
    gemm_tc<5><<<dim3(DMODEL / 128, MROWS / 128), 256, SMEM_BYT>>>(
        inT, NUML, w1, b1, nullptr, DMODEL, DMODEL, NUML, embh, embl);

    // join: layer loop needs the split weights on both streams
    cudaStreamWaitEvent(0, evW, 0);

    for (int layer = 0; layer < 2; ++layer) {
        cudaEventRecord(evF[layer], 0);
        cudaStreamWaitEvent(s2, evF[layer], 0);

        for (int dir = 0; dir < 2; ++dir) {
            const int off = dir * 2 + layer;
            cudaStream_t st = dir ? s2 : 0;
            float* xz  = dir ? xzB : xzA;
            float* xc  = dir ? xcB : xcA;
            float* xd  = dir ? xdB : xdA;
            float* dtp = dir ? dtB : dtA;
            __nv_bfloat16* ysh = dir ? yshB : yshA;
            __nv_bfloat16* ysl = dir ? yslB : yslA;
            float* accD = dir ? acc2 : acc;

            const __nv_bfloat16* Winh = winh + (size_t)off * 2 * DINNER * DMODEL;
            const __nv_bfloat16* Winl = winl + (size_t)off * 2 * DINNER * DMODEL;
            const __nv_bfloat16* Wouh = wouth + (size_t)off * DMODEL * DINNER;
            const __nv_bfloat16* Woul = woutl + (size_t)off * DMODEL * DINNER;
            const float* cw   = conv_w + (size_t)off * DINNER * 4;
            const float* cb   = conv_b + (size_t)off * DINNER;
            const float* Wxp  = w_xp   + (size_t)off * 64 * DINNER;
            const float* Wdt  = w_dt   + (size_t)off * DINNER * DTRANK;
            const float* bdt  = b_dt   + (size_t)off * DINNER;
            const float* Al   = a_log  + (size_t)off * DINNER * DSTATE;
            const float* Dp   = d_skip + (size_t)off * DINNER;

            gemm_bf<0><<<dim3(2 * DINNER / 128, MROWS / 128), 256, BF_SMEM, st>>>(
                embh, embl, Winh, Winl, nullptr, xz, 2 * DINNER, DMODEL);

            conv_silu_k<<<(MROWS / 4) * (DINNER / 4) / 256, 256, 0, st>>>(xz, cw, cb, xc, dir);

            gemm_tc<0><<<dim3(1, MROWS / 128), 256, SMEM_BYT, st>>>(
                xc, DINNER, Wxp, nullptr, xd, 64, 64, DINNER, nullptr, nullptr);

            gemm_tc<4><<<dim3(DINNER / 128, MROWS / 128), 256, SMEM_BYT, st>>>(
                xd, 64, Wdt, bdt, dtp, DINNER, DINNER, DTRANK, nullptr, nullptr);

            scan_k<<<(BATCH * DINNER * 4) / 256, 256, 0, st>>>(
                (const float2*)dtp, xc, xd, xz, Al, Dp, ysh, ysl, dir);

            gemm_bf<0><<<dim3(DMODEL / 128, MROWS / 128), 256, BF_SMEM, st>>>(
                ysh, ysl, Wouh, Woul, nullptr, accD, DMODEL, DINNER);
        }

        cudaEventRecord(evJ[layer], s2);
        cudaStreamWaitEvent(0, evJ[layer], 0);

        silu3_k<<<(MROWS * DMODEL / 4 + 255) / 256, 256>>>(
            (const float4*)acc, (const float4*)acc2, embh, embl, MROWS * DMODEL / 4);
    }

    // final projection with fused bias + transposed store directly into d_out
    gemm_bf<4><<<dim3(PREDP / 128, MROWS / 128), 256, BF_SMEM>>>(
        embh, embl, w2h, w2l, b2p, (float*)d_out, 0, DMODEL);
}